// round 8
// baseline (speedup 1.0000x reference)
#include <cuda_runtime.h>
#include <cuda_bf16.h>
#include <math.h>

// ---------------- problem constants ----------------
#define S_LEN   2048
#define BATCH   2
#define DMODEL  1024
#define NHEADS  16
#define DK      64
#define NEGV    (-1.0e9f)

#define OUT_ELEMS  ((size_t)S_LEN * BATCH * DMODEL)                 // 4,194,304
#define ATTN_ELEMS ((size_t)BATCH * NHEADS * S_LEN * S_LEN)         // 134,217,728

typedef __nv_bfloat16  bf16;
typedef __nv_bfloat162 bf162;

#define XS_SLAB ((size_t)4096 * 3072)
#define WS_SLAB ((size_t)1024 * 3072)

// ---------------- scratch (static device globals; no runtime alloc) ----------
__device__ bf16  g_Xs [3 * XS_SLAB];           // split activations [hi|hi|lo] x {q,k,v / ctx}
__device__ bf16  g_Ws [4 * WS_SLAB];           // split weights     [hi|lo|hi] x {Wq,Wk,Wv,Wo}
__device__ bf16  g_Qhi[(size_t)32 * 2048 * 64];
__device__ bf16  g_Qlo[(size_t)32 * 2048 * 64];
__device__ bf16  g_Khi[(size_t)32 * 2048 * 64];
__device__ bf16  g_Klo[(size_t)32 * 2048 * 64];
__device__ bf16  g_Vhi[(size_t)32 * 2048 * 64];
__device__ bf16  g_Vlo[(size_t)32 * 2048 * 64];
__device__ bf16  g_VThi[(size_t)32 * 64 * 2048];
__device__ bf16  g_VTlo[(size_t)32 * 64 * 2048];
__device__ float g_CT[(size_t)4096 * 1024];    // context (s,b,D)
__device__ float2 g_stats[32 * 2048];          // per-row {max, 1/Z}
__device__ float g_attn_fb[ATTN_ELEMS];        // fallback if attn not in output

// ---------------- PTX helpers ----------------
__device__ __forceinline__ void cp16(const void* smem_dst, const void* gmem_src) {
    unsigned d = (unsigned)__cvta_generic_to_shared(smem_dst);
    asm volatile("cp.async.cg.shared.global [%0], [%1], 16;" :: "r"(d), "l"(gmem_src));
}
__device__ __forceinline__ void cp_commit() { asm volatile("cp.async.commit_group;"); }
__device__ __forceinline__ void cp_wait0()  { asm volatile("cp.async.wait_group 0;"); }

__device__ __forceinline__ unsigned smem_u32(const void* p) {
    return (unsigned)__cvta_generic_to_shared(p);
}

__device__ __forceinline__ void mma_bf16(float& d0, float& d1, float& d2, float& d3,
                                         unsigned a0, unsigned a1, unsigned a2, unsigned a3,
                                         unsigned b0, unsigned b1)
{
    asm volatile(
        "mma.sync.aligned.m16n8k16.row.col.f32.bf16.bf16.f32 "
        "{%0,%1,%2,%3},{%4,%5,%6,%7},{%8,%9},{%0,%1,%2,%3};\n"
        : "+f"(d0), "+f"(d1), "+f"(d2), "+f"(d3)
        : "r"(a0), "r"(a1), "r"(a2), "r"(a3), "r"(b0), "r"(b1));
}

__device__ __forceinline__ void ldsm4(unsigned& r0, unsigned& r1, unsigned& r2, unsigned& r3,
                                      unsigned addr)
{
    asm volatile("ldmatrix.sync.aligned.m8n8.x4.shared.b16 {%0,%1,%2,%3}, [%4];"
                 : "=r"(r0), "=r"(r1), "=r"(r2), "=r"(r3) : "r"(addr));
}

// ===========================================================================
// prep kernels: fp32 (rows x 1024) -> bf16 (rows x 3072) augmented-K split.
// pattern 0 (activations): [hi | hi | lo]   pattern 1 (weights): [hi | lo | hi]
// ===========================================================================
__device__ __forceinline__ void split_store(const float* src, bf16* dst,
                                            size_t p, int pattern)
{
    int row = (int)(p >> 9);
    int cp  = (int)(p & 511);
    float2 v = *(const float2*)(src + (size_t)row * 1024 + cp * 2);
    bf16 h0 = __float2bfloat16_rn(v.x);
    bf16 h1 = __float2bfloat16_rn(v.y);
    bf16 l0 = __float2bfloat16_rn(v.x - __bfloat162float(h0));
    bf16 l1 = __float2bfloat16_rn(v.y - __bfloat162float(h1));
    bf162 h2; h2.x = h0; h2.y = h1;
    bf162 l2; l2.x = l0; l2.y = l1;
    bf162* d = (bf162*)(dst + (size_t)row * 3072 + cp * 2);
    if (pattern == 0) { d[0] = h2; d[512] = h2; d[1024] = l2; }
    else              { d[0] = h2; d[512] = l2; d[1024] = h2; }
}

__global__ void __launch_bounds__(256)
prep_qkv(const float* __restrict__ q, const float* __restrict__ k,
         const float* __restrict__ v, bf16* __restrict__ dst)
{
    size_t p = (size_t)blockIdx.x * 256 + threadIdx.x;
    if (p >= (size_t)4096 * 512) return;
    const float* src = (blockIdx.z == 0) ? q : (blockIdx.z == 1) ? k : v;
    split_store(src, dst + blockIdx.z * XS_SLAB, p, 0);
}

__global__ void __launch_bounds__(256)
prep_w(const float* __restrict__ w0, const float* __restrict__ w1,
       const float* __restrict__ w2, const float* __restrict__ w3,
       bf16* __restrict__ dst)
{
    size_t p = (size_t)blockIdx.x * 256 + threadIdx.x;
    if (p >= (size_t)1024 * 512) return;
    const float* src = (blockIdx.z == 0) ? w0 : (blockIdx.z == 1) ? w1
                     : (blockIdx.z == 2) ? w2 : w3;
    split_store(src, dst + blockIdx.z * WS_SLAB, p, 1);
}

__global__ void __launch_bounds__(256)
prep_one(const float* __restrict__ src, bf16* __restrict__ dst, int rows)
{
    size_t p = (size_t)blockIdx.x * 256 + threadIdx.x;
    if (p >= (size_t)rows * 512) return;
    split_store(src, dst, p, 0);
}

// ===========================================================================
// gemm_bf16: C[m,n] = sum_k A[m,k]*B[n,k], NT, K=3072.
// CTA tile 128(M) x 64(N), BK=32, 256 thr = 8 warps, warp = 16 rows x 64 cols.
// __launch_bounds__(256,3) -> <=85 regs -> 3 CTAs/SM (24 warps).
// z-batched: blockIdx.z selects activation/weight slab + destination.
// mode 0: fp32 C (+bias). mode 1: split-bf16 scatter into (b,h,s,d).
// ===========================================================================
#define GP 40   // padded K-stride (80B = 5x16B units, odd -> conflict-free ldmatrix)
__global__ void __launch_bounds__(256, 3)
gemm_bf16(const bf16* __restrict__ Xs, const bf16* __restrict__ Ws,
          int mode, float* __restrict__ C, const float* __restrict__ bias,
          bf16* __restrict__ Qh, bf16* __restrict__ Ql,
          bf16* __restrict__ Kh, bf16* __restrict__ Kl,
          bf16* __restrict__ Vh, bf16* __restrict__ Vl)
{
    __shared__ __align__(16) bf16 sA[2][128 * GP];
    __shared__ __align__(16) bf16 sB[2][64 * GP];

    const int z = blockIdx.z;
    const bf16* A = Xs + (size_t)z * XS_SLAB;
    const bf16* B = Ws + (size_t)z * WS_SLAB;
    bf16* Dhi = (z == 0) ? Qh : (z == 1) ? Kh : Vh;
    bf16* Dlo = (z == 0) ? Ql : (z == 1) ? Kl : Vl;

    const int t = threadIdx.x;
    const int wid = t >> 5, lane = t & 31;
    const int r0 = lane >> 2, c0 = (lane & 3) * 2;
    const int g  = lane >> 3, lr = lane & 7;
    const int bm = blockIdx.y * 128, bn = blockIdx.x * 64;
    const int K = 3072;

    float acc[8][4];
    #pragma unroll
    for (int i = 0; i < 8; i++)
        #pragma unroll
        for (int j = 0; j < 4; j++) acc[i][j] = 0.f;

    // loaders: A 512 chunks (2/thread), B 256 chunks (1/thread)
    const int arow0 = t >> 2,        ack0 = t & 3;          // +64 rows for 2nd
    const int brow  = t >> 2,        bck  = t & 3;

    cp16(&sA[0][arow0 * GP + ack0 * 8],        A + (size_t)(bm + arow0) * K + ack0 * 8);
    cp16(&sA[0][(arow0 + 64) * GP + ack0 * 8], A + (size_t)(bm + arow0 + 64) * K + ack0 * 8);
    cp16(&sB[0][brow * GP + bck * 8],          B + (size_t)(bn + brow) * K + bck * 8);
    cp_commit();

    const unsigned uA0 = smem_u32(&sA[0][0]), uA1 = smem_u32(&sA[1][0]);
    const unsigned uB0 = smem_u32(&sB[0][0]), uB1 = smem_u32(&sB[1][0]);

    const int aoff = (wid * 16 + (g & 1) * 8 + lr) * GP + (g >> 1) * 8;
    const int boff_row = (g >> 1) * 8 + lr;
    const int boff_k   = (g & 1) * 8;

    int buf = 0;
    for (int kt = 0; kt < K / 32; kt++) {
        cp_wait0();
        __syncthreads();
        if (kt + 1 < K / 32) {
            int k0 = (kt + 1) * 32;
            bf16* dA = &sA[buf ^ 1][0];
            bf16* dB = &sB[buf ^ 1][0];
            cp16(&dA[arow0 * GP + ack0 * 8],        A + (size_t)(bm + arow0) * K + k0 + ack0 * 8);
            cp16(&dA[(arow0 + 64) * GP + ack0 * 8], A + (size_t)(bm + arow0 + 64) * K + k0 + ack0 * 8);
            cp16(&dB[brow * GP + bck * 8],          B + (size_t)(bn + brow) * K + k0 + bck * 8);
            cp_commit();
        }

        const unsigned uA = buf ? uA1 : uA0;
        const unsigned uB = buf ? uB1 : uB0;
        #pragma unroll
        for (int ks = 0; ks < 2; ks++) {
            const int kk = ks * 16;
            unsigned a0, a1, a2, a3;
            ldsm4(a0, a1, a2, a3, uA + (unsigned)((aoff + kk) * 2));
            #pragma unroll
            for (int p = 0; p < 4; p++) {
                unsigned b0, b1, b2, b3;
                ldsm4(b0, b1, b2, b3,
                      uB + (unsigned)(((p * 16 + boff_row) * GP + kk + boff_k) * 2));
                mma_bf16(acc[2*p][0], acc[2*p][1], acc[2*p][2], acc[2*p][3],
                         a0, a1, a2, a3, b0, b1);
                mma_bf16(acc[2*p+1][0], acc[2*p+1][1], acc[2*p+1][2], acc[2*p+1][3],
                         a0, a1, a2, a3, b2, b3);
            }
        }
        buf ^= 1;
    }

    const int mA = bm + wid * 16 + r0, mB = mA + 8;
    #pragma unroll
    for (int nt = 0; nt < 8; nt++) {
        int n = bn + nt * 8 + c0;
        if (mode == 0) {
            float bx = bias[n], by = bias[n + 1];
            *(float2*)(C + (size_t)mA * 1024 + n) = make_float2(acc[nt][0] + bx, acc[nt][1] + by);
            *(float2*)(C + (size_t)mB * 1024 + n) = make_float2(acc[nt][2] + bx, acc[nt][3] + by);
        } else {
            int h = n >> 6, d = n & 63;
            #pragma unroll
            for (int rr = 0; rr < 2; rr++) {
                int m = rr ? mB : mA;
                float v0 = acc[nt][rr * 2], v1 = acc[nt][rr * 2 + 1];
                int s = m >> 1, b = m & 1;
                size_t off = (((size_t)(b * NHEADS + h) * S_LEN) + s) * 64 + d;
                bf16 h0 = __float2bfloat16_rn(v0);
                bf16 h1 = __float2bfloat16_rn(v1);
                bf16 l0 = __float2bfloat16_rn(v0 - __bfloat162float(h0));
                bf16 l1 = __float2bfloat16_rn(v1 - __bfloat162float(h1));
                bf162 hh; hh.x = h0; hh.y = h1;
                bf162 ll; ll.x = l0; ll.y = l1;
                *(bf162*)(Dhi + off) = hh;
                *(bf162*)(Dlo + off) = ll;
            }
        }
    }
}

// ===========================================================================
// transpose_bf16: (b,h,s,64) -> (b,h,64,2048)
// ===========================================================================
__global__ void __launch_bounds__(256)
transpose_bf16(const bf16* __restrict__ src, bf16* __restrict__ dst)
{
    __shared__ bf16 tl[32][34];
    const int bh = blockIdx.z;
    const bf16* s = src + (size_t)bh * 2048 * 64;
    bf16*       d = dst + (size_t)bh * 64 * 2048;
    const int s0 = blockIdx.x * 32, d0 = blockIdx.y * 32;
    const int x = threadIdx.x, y = threadIdx.y;
    #pragma unroll
    for (int i = 0; i < 32; i += 8)
        tl[y + i][x] = s[(size_t)(s0 + y + i) * 64 + d0 + x];
    __syncthreads();
    #pragma unroll
    for (int i = 0; i < 32; i += 8)
        d[(size_t)(d0 + y + i) * 2048 + s0 + x] = tl[x][y + i];
}

// ===========================================================================
// qk_scores: per CTA (128 q rows, h, b): 3-product bf16 MMA over d=64,
// mask + scale + online softmax stats, raw masked scores -> attn buffer.
// ===========================================================================
#define QP 72   // 144B = 9x16B units, odd -> conflict-free ldmatrix
__global__ void __launch_bounds__(256)
qk_scores(const bf16* __restrict__ Qhi, const bf16* __restrict__ Qlo,
          const bf16* __restrict__ Khi, const bf16* __restrict__ Klo,
          const int* __restrict__ mask, const int* __restrict__ kpm,
          float* __restrict__ attn, float2* __restrict__ stats)
{
    extern __shared__ __align__(16) bf16 smq[];
    bf16* sQh = smq;
    bf16* sQl = smq + 9216;
    bf16* sK  = smq + 18432;

    const int t = threadIdx.x;
    const int wid = t >> 5, lane = t & 31;
    const int r0 = lane >> 2, c0 = (lane & 3) * 2;
    const int g  = lane >> 3, lr = lane & 7;
    const int q0 = blockIdx.x * 128, h = blockIdx.y, b = blockIdx.z;
    const size_t bh = (size_t)(b * NHEADS + h);

    {
        const size_t base = bh * 2048 + q0;
        #pragma unroll
        for (int i = 0; i < 4; i++) {
            int f = i * 256 + t; int row = f >> 3, ck = f & 7;
            cp16(&sQh[row * QP + ck * 8], Qhi + (base + row) * 64 + ck * 8);
            cp16(&sQl[row * QP + ck * 8], Qlo + (base + row) * 64 + ck * 8);
        }
    }
    {
        const size_t base = bh * 2048;
        #pragma unroll
        for (int i = 0; i < 4; i++) {
            int f = i * 256 + t; int row = f >> 3, ck = f & 7;
            cp16(&sK[0 * 9216 + row * QP + ck * 8], Khi + (base + row) * 64 + ck * 8);
            cp16(&sK[1 * 9216 + row * QP + ck * 8], Klo + (base + row) * 64 + ck * 8);
        }
    }
    cp_commit();

    const unsigned uQh = smem_u32(sQh), uQl = smem_u32(sQl), uK = smem_u32(sK);

    float mrA = -INFINITY, zrA = 0.f, mrB = -INFINITY, zrB = 0.f;
    const int qA = q0 + wid * 16 + r0;
    const int* maskA = mask + (size_t)qA * S_LEN;
    const int* maskB = maskA + (size_t)8 * S_LEN;
    const int* kpmb  = kpm + b * S_LEN;
    float* attnA = attn + (bh * S_LEN + qA) * (size_t)S_LEN;
    float* attnB = attnA + (size_t)8 * S_LEN;

    const int aoff = (wid * 16 + (g & 1) * 8 + lr) * QP + (g >> 1) * 8;
    const int boff_row = (g >> 1) * 8 + lr;
    const int boff_k   = (g & 1) * 8;

    int buf = 0;
    for (int kt = 0; kt < 16; kt++) {
        cp_wait0();
        __syncthreads();
        if (kt < 15) {
            const size_t base = bh * 2048 + (size_t)(kt + 1) * 128;
            bf16* dh = sK + ((buf ^ 1) * 2 + 0) * 9216;
            bf16* dl = sK + ((buf ^ 1) * 2 + 1) * 9216;
            #pragma unroll
            for (int i = 0; i < 4; i++) {
                int f = i * 256 + t; int row = f >> 3, ck = f & 7;
                cp16(&dh[row * QP + ck * 8], Khi + (base + row) * 64 + ck * 8);
                cp16(&dl[row * QP + ck * 8], Klo + (base + row) * 64 + ck * 8);
            }
            cp_commit();
        }

        float acc[16][4];
        #pragma unroll
        for (int i = 0; i < 16; i++)
            #pragma unroll
            for (int j = 0; j < 4; j++) acc[i][j] = 0.f;

        #pragma unroll
        for (int pr = 0; pr < 3; pr++) {
            const unsigned aU = (pr < 2) ? uQh : uQl;
            const unsigned bU = uK + (unsigned)(((buf * 2 + (pr == 1 ? 1 : 0)) * 9216) * 2);
            #pragma unroll
            for (int ks = 0; ks < 4; ks++) {
                const int kk = ks * 16;
                unsigned a0, a1, a2, a3;
                ldsm4(a0, a1, a2, a3, aU + (unsigned)((aoff + kk) * 2));
                #pragma unroll
                for (int p = 0; p < 8; p++) {
                    unsigned b0, b1, b2, b3;
                    ldsm4(b0, b1, b2, b3,
                          bU + (unsigned)(((p * 16 + boff_row) * QP + kk + boff_k) * 2));
                    mma_bf16(acc[2*p][0], acc[2*p][1], acc[2*p][2], acc[2*p][3],
                             a0, a1, a2, a3, b0, b1);
                    mma_bf16(acc[2*p+1][0], acc[2*p+1][1], acc[2*p+1][2], acc[2*p+1][3],
                             a0, a1, a2, a3, b2, b3);
                }
            }
        }

        const int kbase = kt * 128;
        float tmA = -INFINITY, tmB = -INFINITY;
        #pragma unroll
        for (int nt = 0; nt < 16; nt++) {
            int kg = kbase + nt * 8 + c0;
            int2 kp = *(const int2*)&kpmb[kg];
            int2 ma = *(const int2*)&maskA[kg];
            int2 mb = *(const int2*)&maskB[kg];
            float v0 = (kp.x && ma.x) ? acc[nt][0] * 0.125f : NEGV;
            float v1 = (kp.y && ma.y) ? acc[nt][1] * 0.125f : NEGV;
            float v2 = (kp.x && mb.x) ? acc[nt][2] * 0.125f : NEGV;
            float v3 = (kp.y && mb.y) ? acc[nt][3] * 0.125f : NEGV;
            acc[nt][0] = v0; acc[nt][1] = v1; acc[nt][2] = v2; acc[nt][3] = v3;
            tmA = fmaxf(tmA, fmaxf(v0, v1));
            tmB = fmaxf(tmB, fmaxf(v2, v3));
        }
        tmA = fmaxf(tmA, __shfl_xor_sync(0xffffffffu, tmA, 1));
        tmA = fmaxf(tmA, __shfl_xor_sync(0xffffffffu, tmA, 2));
        tmB = fmaxf(tmB, __shfl_xor_sync(0xffffffffu, tmB, 1));
        tmB = fmaxf(tmB, __shfl_xor_sync(0xffffffffu, tmB, 2));

        float mnA = fmaxf(mrA, tmA), mnB = fmaxf(mrB, tmB);
        float corA = __expf(mrA - mnA), corB = __expf(mrB - mnB);
        float zlA = 0.f, zlB = 0.f;
        #pragma unroll
        for (int nt = 0; nt < 16; nt++) {
            zlA += __expf(acc[nt][0] - mnA) + __expf(acc[nt][1] - mnA);
            zlB += __expf(acc[nt][2] - mnB) + __expf(acc[nt][3] - mnB);
        }
        zlA += __shfl_xor_sync(0xffffffffu, zlA, 1);
        zlA += __shfl_xor_sync(0xffffffffu, zlA, 2);
        zlB += __shfl_xor_sync(0xffffffffu, zlB, 1);
        zlB += __shfl_xor_sync(0xffffffffu, zlB, 2);
        zrA = zrA * corA + zlA; mrA = mnA;
        zrB = zrB * corB + zlB; mrB = mnB;

        #pragma unroll
        for (int nt = 0; nt < 16; nt++) {
            int kg = kbase + nt * 8 + c0;
            *(float2*)&attnA[kg] = make_float2(acc[nt][0], acc[nt][1]);
            *(float2*)&attnB[kg] = make_float2(acc[nt][2], acc[nt][3]);
        }
        buf ^= 1;
    }

    if ((lane & 3) == 0) {
        stats[bh * S_LEN + qA]     = make_float2(mrA, 1.f / zrA);
        stats[bh * S_LEN + qA + 8] = make_float2(mrB, 1.f / zrB);
    }
}

// ===========================================================================
// attn_av: normalize P in place (required attn output), split P to bf16 hi/lo
// smem, 3-product ldmatrix MMA with VT hi/lo tiles, ctx written in (s,b,D).
// ===========================================================================
#define PP 136  // 272B = 17x16B units, odd -> conflict-free ldmatrix
__global__ void __launch_bounds__(256)
attn_av(const bf16* __restrict__ VThi, const bf16* __restrict__ VTlo,
        float* __restrict__ attn, const float2* __restrict__ stats,
        float* __restrict__ ctx)
{
    extern __shared__ __align__(16) bf16 smv[];
    bf16* sPh = smv;
    bf16* sPl = smv + 17408;
    bf16* sVh = smv + 34816;
    bf16* sVl = smv + 43520;
    float2* st = (float2*)(smv + 52224);

    const int t = threadIdx.x;
    const int wid = t >> 5, lane = t & 31;
    const int r0 = lane >> 2, c0 = (lane & 3) * 2;
    const int g  = lane >> 3, lr = lane & 7;
    const int q0 = blockIdx.x * 128, h = blockIdx.y, b = blockIdx.z;
    const size_t bh = (size_t)(b * NHEADS + h);

    if (t < 128) st[t] = stats[bh * S_LEN + q0 + t];

    float* attnp = attn + (bh * S_LEN + q0) * (size_t)S_LEN;
    const bf16* Vh = VThi + bh * (size_t)64 * 2048;
    const bf16* Vl = VTlo + bh * (size_t)64 * 2048;

    const unsigned uPh = smem_u32(sPh), uPl = smem_u32(sPl);
    const unsigned uVh = smem_u32(sVh), uVl = smem_u32(sVl);
    const int aoff = (wid * 16 + (g & 1) * 8 + lr) * PP + (g >> 1) * 8;
    const int boff_row = (g >> 1) * 8 + lr;
    const int boff_k   = (g & 1) * 8;

    float acc[8][4];
    #pragma unroll
    for (int i = 0; i < 8; i++)
        #pragma unroll
        for (int j = 0; j < 4; j++) acc[i][j] = 0.f;

    for (int kt = 0; kt < 16; kt++) {
        __syncthreads();

        #pragma unroll
        for (int i = 0; i < 4; i++) {
            int f = i * 256 + t; int row = f >> 4, ck = f & 15;
            cp16(&sVh[row * PP + ck * 8], Vh + (size_t)row * 2048 + kt * 128 + ck * 8);
            cp16(&sVl[row * PP + ck * 8], Vl + (size_t)row * 2048 + kt * 128 + ck * 8);
        }
        cp_commit();

        #pragma unroll
        for (int i = 0; i < 16; i++) {
            int f = i * 256 + t; int row = f >> 5, k4 = (f & 31) * 4;
            float* gp = attnp + (size_t)row * S_LEN + kt * 128 + k4;
            float4 s4 = *(const float4*)gp;
            float2 mz = st[row];
            float4 p4;
            p4.x = __expf(s4.x - mz.x) * mz.y;
            p4.y = __expf(s4.y - mz.x) * mz.y;
            p4.z = __expf(s4.z - mz.x) * mz.y;
            p4.w = __expf(s4.w - mz.x) * mz.y;
            *(float4*)gp = p4;
            bf16 h0 = __float2bfloat16_rn(p4.x), h1 = __float2bfloat16_rn(p4.y);
            bf16 h2 = __float2bfloat16_rn(p4.z), h3 = __float2bfloat16_rn(p4.w);
            bf162 ha; ha.x = h0; ha.y = h1;
            bf162 hb; hb.x = h2; hb.y = h3;
            bf162 la; la.x = __float2bfloat16_rn(p4.x - __bfloat162float(h0));
                      la.y = __float2bfloat16_rn(p4.y - __bfloat162float(h1));
            bf162 lb; lb.x = __float2bfloat16_rn(p4.z - __bfloat162float(h2));
                      lb.y = __float2bfloat16_rn(p4.w - __bfloat162float(h3));
            *(bf162*)&sPh[row * PP + k4]     = ha;
            *(bf162*)&sPh[row * PP + k4 + 2] = hb;
            *(bf162*)&sPl[row * PP + k4]     = la;
            *(bf162*)&sPl[row * PP + k4 + 2] = lb;
        }
        cp_wait0();
        __syncthreads();

        #pragma unroll
        for (int pr = 0; pr < 3; pr++) {
            const unsigned aU = (pr < 2) ? uPh : uPl;
            const unsigned bU = (pr == 1) ? uVl : uVh;
            #pragma unroll
            for (int ks = 0; ks < 8; ks++) {
                const int kk = ks * 16;
                unsigned a0, a1, a2, a3;
                ldsm4(a0, a1, a2, a3, aU + (unsigned)((aoff + kk) * 2));
                #pragma unroll
                for (int p = 0; p < 4; p++) {
                    unsigned b0, b1, b2, b3;
                    ldsm4(b0, b1, b2, b3,
                          bU + (unsigned)(((p * 16 + boff_row) * PP + kk + boff_k) * 2));
                    mma_bf16(acc[2*p][0], acc[2*p][1], acc[2*p][2], acc[2*p][3],
                             a0, a1, a2, a3, b0, b1);
                    mma_bf16(acc[2*p+1][0], acc[2*p+1][1], acc[2*p+1][2], acc[2*p+1][3],
                             a0, a1, a2, a3, b2, b3);
                }
            }
        }
    }

    const int qA = q0 + wid * 16 + r0, qB = qA + 8;
    #pragma unroll
    for (int nt = 0; nt < 8; nt++) {
        int d = h * 64 + nt * 8 + c0;
        *(float2*)&ctx[((size_t)qA * BATCH + b) * DMODEL + d] =
            make_float2(acc[nt][0], acc[nt][1]);
        *(float2*)&ctx[((size_t)qB * BATCH + b) * DMODEL + d] =
            make_float2(acc[nt][2], acc[nt][3]);
    }
}

// ===========================================================================
extern "C" void kernel_launch(void* const* d_in, const int* in_sizes, int n_in,
                              void* d_out, int out_size)
{
    const float* query = (const float*)d_in[0];
    const float* key   = (const float*)d_in[1];
    const float* value = (const float*)d_in[2];
    const int*   mask  = (const int*)  d_in[3];
    const int*   kpm   = (const int*)  d_in[4];
    const float* Wq    = (const float*)d_in[5];
    const float* Wk    = (const float*)d_in[6];
    const float* Wv    = (const float*)d_in[7];
    const float* Wo    = (const float*)d_in[8];
    const float* bo    = (const float*)d_in[9];

    float* out = (float*)d_out;
    const int write_attn = ((size_t)out_size >= OUT_ELEMS + ATTN_ELEMS) ? 1 : 0;

    bf16 *pXs, *pWs, *pQh, *pQl, *pKh, *pKl, *pVh, *pVl, *pVTh, *pVTl;
    float *pCT, *pAfb;
    float2* pST;
    cudaGetSymbolAddress((void**)&pXs,  g_Xs);
    cudaGetSymbolAddress((void**)&pWs,  g_Ws);
    cudaGetSymbolAddress((void**)&pQh,  g_Qhi);
    cudaGetSymbolAddress((void**)&pQl,  g_Qlo);
    cudaGetSymbolAddress((void**)&pKh,  g_Khi);
    cudaGetSymbolAddress((void**)&pKl,  g_Klo);
    cudaGetSymbolAddress((void**)&pVh,  g_Vhi);
    cudaGetSymbolAddress((void**)&pVl,  g_Vlo);
    cudaGetSymbolAddress((void**)&pVTh, g_VThi);
    cudaGetSymbolAddress((void**)&pVTl, g_VTlo);
    cudaGetSymbolAddress((void**)&pCT,  g_CT);
    cudaGetSymbolAddress((void**)&pST,  g_stats);
    cudaGetSymbolAddress((void**)&pAfb, g_attn_fb);

    float* attn = write_attn ? (out + OUT_ELEMS) : pAfb;

    const int M = S_LEN * BATCH;         // 4096
    dim3 ggrid3(1024 / 64, M / 128, 3);  // (16, 32, 3) batched QKV
    dim3 ggrid1(1024 / 64, M / 128, 1);  // out-proj

    // batched splits: all 4 weights; q,k,v activations
    prep_w  <<<dim3(2048, 1, 4), 256>>>(Wq, Wk, Wv, Wo, pWs);
    prep_qkv<<<dim3(8192, 1, 3), 256>>>(query, key, value, pXs);

    // Q/K/V projections in ONE launch (z selects slab + dst), split layout out
    gemm_bf16<<<ggrid3, 256>>>(pXs, pWs, 1, nullptr, nullptr,
                               pQh, pQl, pKh, pKl, pVh, pVl);

    // V -> d-major
    dim3 tgrid(2048 / 32, 64 / 32, 32);
    transpose_bf16<<<tgrid, dim3(32, 8)>>>(pVh, pVTh);
    transpose_bf16<<<tgrid, dim3(32, 8)>>>(pVl, pVTl);

    // QK^T + masks + online stats
    const int smq_bytes = 55296 * 2;
    cudaFuncSetAttribute(qk_scores, cudaFuncAttributeMaxDynamicSharedMemorySize, smq_bytes);
    dim3 agrid(S_LEN / 128, NHEADS, BATCH);
    qk_scores<<<agrid, 256, smq_bytes>>>(pQh, pQl, pKh, pKl, mask, kpm, attn, pST);

    // normalize + AV -> ctx
    const int smv_bytes = 52224 * 2 + 128 * 8;
    cudaFuncSetAttribute(attn_av, cudaFuncAttributeMaxDynamicSharedMemorySize, smv_bytes);
    attn_av<<<agrid, 256, smv_bytes>>>(pVTh, pVTl, attn, pST, pCT);

    // output projection (+bias): reuse slab 0 for split ctx
    prep_one<<<8192, 256>>>(pCT, pXs, M);
    gemm_bf16<<<ggrid1, 256>>>(pXs, pWs + 3 * WS_SLAB, 0, out, bo,
                               nullptr, nullptr, nullptr, nullptr, nullptr, nullptr);
}

// round 10
// speedup vs baseline: 1.4910x; 1.4910x over previous
#include <cuda_runtime.h>
#include <cuda_bf16.h>
#include <math.h>

// ---------------- problem constants ----------------
#define S_LEN   2048
#define BATCH   2
#define DMODEL  1024
#define NHEADS  16
#define DK      64
#define NEGV    (-1.0e9f)

#define OUT_ELEMS  ((size_t)S_LEN * BATCH * DMODEL)                 // 4,194,304
#define ATTN_ELEMS ((size_t)BATCH * NHEADS * S_LEN * S_LEN)         // 134,217,728

typedef __nv_bfloat16  bf16;
typedef __nv_bfloat162 bf162;

#define XH_SLAB ((size_t)4096 * 1024)
#define WH_SLAB ((size_t)1024 * 1024)

// ---------------- scratch (static device globals; no runtime alloc) ----------
__device__ bf16  g_Xhi[3 * XH_SLAB];           // activation hi x {q,k,v / ctx}
__device__ bf16  g_Xlo[3 * XH_SLAB];           // activation lo
__device__ bf16  g_Whi[4 * WH_SLAB];           // weight hi x {Wq,Wk,Wv,Wo}
__device__ bf16  g_Wlo[4 * WH_SLAB];           // weight lo
__device__ bf16  g_Qhi[(size_t)32 * 2048 * 64];
__device__ bf16  g_Qlo[(size_t)32 * 2048 * 64];
__device__ bf16  g_Khi[(size_t)32 * 2048 * 64];
__device__ bf16  g_Klo[(size_t)32 * 2048 * 64];
__device__ bf16  g_Vhi[(size_t)32 * 2048 * 64];
__device__ bf16  g_Vlo[(size_t)32 * 2048 * 64];
__device__ bf16  g_VThi[(size_t)32 * 64 * 2048];
__device__ bf16  g_VTlo[(size_t)32 * 64 * 2048];
__device__ float g_CT[(size_t)4096 * 1024];    // context (s,b,D)
__device__ float2 g_stats[32 * 2048];          // per-row {max, 1/Z}
__device__ float g_attn_fb[ATTN_ELEMS];        // fallback if attn not in output

// ---------------- PTX helpers ----------------
__device__ __forceinline__ void cp16(const void* smem_dst, const void* gmem_src) {
    unsigned d = (unsigned)__cvta_generic_to_shared(smem_dst);
    asm volatile("cp.async.cg.shared.global [%0], [%1], 16;" :: "r"(d), "l"(gmem_src));
}
__device__ __forceinline__ void cp_commit() { asm volatile("cp.async.commit_group;"); }
__device__ __forceinline__ void cp_wait0()  { asm volatile("cp.async.wait_group 0;"); }

__device__ __forceinline__ unsigned smem_u32(const void* p) {
    return (unsigned)__cvta_generic_to_shared(p);
}

__device__ __forceinline__ void mma_bf16(float& d0, float& d1, float& d2, float& d3,
                                         unsigned a0, unsigned a1, unsigned a2, unsigned a3,
                                         unsigned b0, unsigned b1)
{
    asm volatile(
        "mma.sync.aligned.m16n8k16.row.col.f32.bf16.bf16.f32 "
        "{%0,%1,%2,%3},{%4,%5,%6,%7},{%8,%9},{%0,%1,%2,%3};\n"
        : "+f"(d0), "+f"(d1), "+f"(d2), "+f"(d3)
        : "r"(a0), "r"(a1), "r"(a2), "r"(a3), "r"(b0), "r"(b1));
}

__device__ __forceinline__ void ldsm4(unsigned& r0, unsigned& r1, unsigned& r2, unsigned& r3,
                                      unsigned addr)
{
    asm volatile("ldmatrix.sync.aligned.m8n8.x4.shared.b16 {%0,%1,%2,%3}, [%4];"
                 : "=r"(r0), "=r"(r1), "=r"(r2), "=r"(r3) : "r"(addr));
}

// ===========================================================================
// prep kernels: fp32 (rows x 1024) -> separate bf16 hi / lo arrays.
// ===========================================================================
__device__ __forceinline__ void split_store2(const float* src, bf16* dh, bf16* dl,
                                             size_t p)
{
    int row = (int)(p >> 9);
    int cp  = (int)(p & 511);
    float2 v = *(const float2*)(src + (size_t)row * 1024 + cp * 2);
    bf16 h0 = __float2bfloat16_rn(v.x);
    bf16 h1 = __float2bfloat16_rn(v.y);
    bf16 l0 = __float2bfloat16_rn(v.x - __bfloat162float(h0));
    bf16 l1 = __float2bfloat16_rn(v.y - __bfloat162float(h1));
    bf162 h2; h2.x = h0; h2.y = h1;
    bf162 l2; l2.x = l0; l2.y = l1;
    *(bf162*)(dh + (size_t)row * 1024 + cp * 2) = h2;
    *(bf162*)(dl + (size_t)row * 1024 + cp * 2) = l2;
}

__global__ void __launch_bounds__(256)
prep_qkv(const float* __restrict__ q, const float* __restrict__ k,
         const float* __restrict__ v, bf16* __restrict__ dh, bf16* __restrict__ dl)
{
    size_t p = (size_t)blockIdx.x * 256 + threadIdx.x;
    if (p >= (size_t)4096 * 512) return;
    const float* src = (blockIdx.z == 0) ? q : (blockIdx.z == 1) ? k : v;
    split_store2(src, dh + blockIdx.z * XH_SLAB, dl + blockIdx.z * XH_SLAB, p);
}

__global__ void __launch_bounds__(256)
prep_w(const float* __restrict__ w0, const float* __restrict__ w1,
       const float* __restrict__ w2, const float* __restrict__ w3,
       bf16* __restrict__ dh, bf16* __restrict__ dl)
{
    size_t p = (size_t)blockIdx.x * 256 + threadIdx.x;
    if (p >= (size_t)1024 * 512) return;
    const float* src = (blockIdx.z == 0) ? w0 : (blockIdx.z == 1) ? w1
                     : (blockIdx.z == 2) ? w2 : w3;
    split_store2(src, dh + blockIdx.z * WH_SLAB, dl + blockIdx.z * WH_SLAB, p);
}

__global__ void __launch_bounds__(256)
prep_one(const float* __restrict__ src, bf16* __restrict__ dh, bf16* __restrict__ dl)
{
    size_t p = (size_t)blockIdx.x * 256 + threadIdx.x;
    if (p >= (size_t)4096 * 512) return;
    split_store2(src, dh, dl, p);
}

// ===========================================================================
// gemm_bf16: C[m,n] = sum_k (Ah+Al)[m,k]*(Bh+Bl)[n,k] (3 products), K=1024.
// CTA 128x128, BK=32, 8 warps, warp = 16 rows x 128 cols.
// Fragment sharing: per k-step load aH,aL once; per n-pair load bH,bL once;
// issue aH*bH + aL*bH + aH*bL into same accumulators.
// DYNAMIC smem: 2 buffers x 4 tiles (Ah,Al,Bh,Bl) x 128*GP bf16 = 81920 B.
// mode 0: fp32 C (+bias). mode 1: split-bf16 scatter into (b,h,s,d).
// ===========================================================================
#define GP 40   // padded K-stride (80B = 5x16B units, odd -> conflict-free ldmatrix)
#define GTILE (128 * GP)                    // elems per tile
#define GEMM_SMEM_BYTES (2 * 4 * GTILE * 2) // 81920
__global__ void __launch_bounds__(256)
gemm_bf16(const bf16* __restrict__ Xh, const bf16* __restrict__ Xl,
          const bf16* __restrict__ Wh, const bf16* __restrict__ Wl,
          int mode, float* __restrict__ C, const float* __restrict__ bias,
          bf16* __restrict__ Qh, bf16* __restrict__ Ql,
          bf16* __restrict__ Kh, bf16* __restrict__ Kl,
          bf16* __restrict__ Vh, bf16* __restrict__ Vl)
{
    extern __shared__ __align__(16) bf16 smg[];   // [buf][arr][GTILE]

    const int z = blockIdx.z;
    const bf16* Ah = Xh + (size_t)z * XH_SLAB;
    const bf16* Al = Xl + (size_t)z * XH_SLAB;
    const bf16* Bh = Wh + (size_t)z * WH_SLAB;
    const bf16* Bl = Wl + (size_t)z * WH_SLAB;
    bf16* Dhi = (z == 0) ? Qh : (z == 1) ? Kh : Vh;
    bf16* Dlo = (z == 0) ? Ql : (z == 1) ? Kl : Vl;

    const int t = threadIdx.x;
    const int wid = t >> 5, lane = t & 31;
    const int r0 = lane >> 2, c0 = (lane & 3) * 2;
    const int g  = lane >> 3, lr = lane & 7;
    const int bm = blockIdx.y * 128, bn = blockIdx.x * 128;
    const int K = 1024;

    float acc[16][4];
    #pragma unroll
    for (int i = 0; i < 16; i++)
        #pragma unroll
        for (int j = 0; j < 4; j++) acc[i][j] = 0.f;

    // loader: 2048 16B chunks per stage (512 per tile), 8 per thread
    auto fill = [&](int buf, int k0) {
        bf16* base = smg + (size_t)buf * 4 * GTILE;
        #pragma unroll
        for (int i = 0; i < 8; i++) {
            int f = i * 256 + t;
            int arr = f >> 9;            // 0=Ah 1=Al 2=Bh 3=Bl
            int idx = f & 511;
            int row = idx >> 2, ck = idx & 3;
            const bf16* gsrc =
                (arr == 0) ? Ah + (size_t)(bm + row) * K + k0 + ck * 8 :
                (arr == 1) ? Al + (size_t)(bm + row) * K + k0 + ck * 8 :
                (arr == 2) ? Bh + (size_t)(bn + row) * K + k0 + ck * 8 :
                             Bl + (size_t)(bn + row) * K + k0 + ck * 8;
            cp16(&base[arr * GTILE + row * GP + ck * 8], gsrc);
        }
        cp_commit();
    };

    fill(0, 0);

    const int aoff = (wid * 16 + (g & 1) * 8 + lr) * GP + (g >> 1) * 8;
    const int boff = ((g >> 1) * 8 + lr) * GP + (g & 1) * 8;

    int buf = 0;
    for (int kt = 0; kt < K / 32; kt++) {
        cp_wait0();
        __syncthreads();
        if (kt + 1 < K / 32) fill(buf ^ 1, (kt + 1) * 32);

        const bf16* sb = smg + (size_t)buf * 4 * GTILE;
        const unsigned uAh = smem_u32(sb + 0 * GTILE);
        const unsigned uAl = smem_u32(sb + 1 * GTILE);
        const unsigned uBh = smem_u32(sb + 2 * GTILE);
        const unsigned uBl = smem_u32(sb + 3 * GTILE);

        #pragma unroll
        for (int ks = 0; ks < 2; ks++) {
            const int kk = ks * 16;
            unsigned ah0, ah1, ah2, ah3, al0, al1, al2, al3;
            ldsm4(ah0, ah1, ah2, ah3, uAh + (unsigned)((aoff + kk) * 2));
            ldsm4(al0, al1, al2, al3, uAl + (unsigned)((aoff + kk) * 2));
            #pragma unroll
            for (int p = 0; p < 8; p++) {
                const unsigned bo = (unsigned)((p * 16 * GP + boff + kk) * 2);
                unsigned bh0, bh1, bh2, bh3, bl0, bl1, bl2, bl3;
                ldsm4(bh0, bh1, bh2, bh3, uBh + bo);
                ldsm4(bl0, bl1, bl2, bl3, uBl + bo);
                mma_bf16(acc[2*p][0], acc[2*p][1], acc[2*p][2], acc[2*p][3],
                         ah0, ah1, ah2, ah3, bh0, bh1);
                mma_bf16(acc[2*p+1][0], acc[2*p+1][1], acc[2*p+1][2], acc[2*p+1][3],
                         ah0, ah1, ah2, ah3, bh2, bh3);
                mma_bf16(acc[2*p][0], acc[2*p][1], acc[2*p][2], acc[2*p][3],
                         al0, al1, al2, al3, bh0, bh1);
                mma_bf16(acc[2*p+1][0], acc[2*p+1][1], acc[2*p+1][2], acc[2*p+1][3],
                         al0, al1, al2, al3, bh2, bh3);
                mma_bf16(acc[2*p][0], acc[2*p][1], acc[2*p][2], acc[2*p][3],
                         ah0, ah1, ah2, ah3, bl0, bl1);
                mma_bf16(acc[2*p+1][0], acc[2*p+1][1], acc[2*p+1][2], acc[2*p+1][3],
                         ah0, ah1, ah2, ah3, bl2, bl3);
            }
        }
        __syncthreads();
        buf ^= 1;
    }

    const int mA = bm + wid * 16 + r0, mB = mA + 8;
    #pragma unroll
    for (int nt = 0; nt < 16; nt++) {
        int n = bn + nt * 8 + c0;
        if (mode == 0) {
            float bx = bias[n], by = bias[n + 1];
            *(float2*)(C + (size_t)mA * 1024 + n) = make_float2(acc[nt][0] + bx, acc[nt][1] + by);
            *(float2*)(C + (size_t)mB * 1024 + n) = make_float2(acc[nt][2] + bx, acc[nt][3] + by);
        } else {
            int h = n >> 6, d = n & 63;
            #pragma unroll
            for (int rr = 0; rr < 2; rr++) {
                int m = rr ? mB : mA;
                float v0 = acc[nt][rr * 2], v1 = acc[nt][rr * 2 + 1];
                int s = m >> 1, b = m & 1;
                size_t off = (((size_t)(b * NHEADS + h) * S_LEN) + s) * 64 + d;
                bf16 h0 = __float2bfloat16_rn(v0);
                bf16 h1 = __float2bfloat16_rn(v1);
                bf16 l0 = __float2bfloat16_rn(v0 - __bfloat162float(h0));
                bf16 l1 = __float2bfloat16_rn(v1 - __bfloat162float(h1));
                bf162 hh; hh.x = h0; hh.y = h1;
                bf162 ll; ll.x = l0; ll.y = l1;
                *(bf162*)(Dhi + off) = hh;
                *(bf162*)(Dlo + off) = ll;
            }
        }
    }
}

// ===========================================================================
// transpose_bf16: (b,h,s,64) -> (b,h,64,2048)
// ===========================================================================
__global__ void __launch_bounds__(256)
transpose_bf16(const bf16* __restrict__ src, bf16* __restrict__ dst)
{
    __shared__ bf16 tl[32][34];
    const int bh = blockIdx.z;
    const bf16* s = src + (size_t)bh * 2048 * 64;
    bf16*       d = dst + (size_t)bh * 64 * 2048;
    const int s0 = blockIdx.x * 32, d0 = blockIdx.y * 32;
    const int x = threadIdx.x, y = threadIdx.y;
    #pragma unroll
    for (int i = 0; i < 32; i += 8)
        tl[y + i][x] = s[(size_t)(s0 + y + i) * 64 + d0 + x];
    __syncthreads();
    #pragma unroll
    for (int i = 0; i < 32; i += 8)
        d[(size_t)(d0 + y + i) * 2048 + s0 + x] = tl[x][y + i];
}

// ===========================================================================
// qk_scores: per CTA (128 q rows, h, b): shared-fragment 3-product MMA,
// mask + scale + online softmax stats, raw masked scores -> attn buffer.
// ===========================================================================
#define QP 72   // 144B = 9x16B units, odd -> conflict-free ldmatrix
__global__ void __launch_bounds__(256)
qk_scores(const bf16* __restrict__ Qhi, const bf16* __restrict__ Qlo,
          const bf16* __restrict__ Khi, const bf16* __restrict__ Klo,
          const int* __restrict__ mask, const int* __restrict__ kpm,
          float* __restrict__ attn, float2* __restrict__ stats)
{
    extern __shared__ __align__(16) bf16 smq[];
    bf16* sQh = smq;
    bf16* sQl = smq + 9216;
    bf16* sK  = smq + 18432;    // [buf][hi/lo] x 9216

    const int t = threadIdx.x;
    const int wid = t >> 5, lane = t & 31;
    const int r0 = lane >> 2, c0 = (lane & 3) * 2;
    const int g  = lane >> 3, lr = lane & 7;
    const int q0 = blockIdx.x * 128, h = blockIdx.y, b = blockIdx.z;
    const size_t bh = (size_t)(b * NHEADS + h);

    {
        const size_t base = bh * 2048 + q0;
        #pragma unroll
        for (int i = 0; i < 4; i++) {
            int f = i * 256 + t; int row = f >> 3, ck = f & 7;
            cp16(&sQh[row * QP + ck * 8], Qhi + (base + row) * 64 + ck * 8);
            cp16(&sQl[row * QP + ck * 8], Qlo + (base + row) * 64 + ck * 8);
        }
    }
    {
        const size_t base = bh * 2048;
        #pragma unroll
        for (int i = 0; i < 4; i++) {
            int f = i * 256 + t; int row = f >> 3, ck = f & 7;
            cp16(&sK[0 * 9216 + row * QP + ck * 8], Khi + (base + row) * 64 + ck * 8);
            cp16(&sK[1 * 9216 + row * QP + ck * 8], Klo + (base + row) * 64 + ck * 8);
        }
    }
    cp_commit();

    const unsigned uQh = smem_u32(sQh), uQl = smem_u32(sQl), uK = smem_u32(sK);

    float mrA = -INFINITY, zrA = 0.f, mrB = -INFINITY, zrB = 0.f;
    const int qA = q0 + wid * 16 + r0;
    const int* maskA = mask + (size_t)qA * S_LEN;
    const int* maskB = maskA + (size_t)8 * S_LEN;
    const int* kpmb  = kpm + b * S_LEN;
    float* attnA = attn + (bh * S_LEN + qA) * (size_t)S_LEN;
    float* attnB = attnA + (size_t)8 * S_LEN;

    const int aoff = (wid * 16 + (g & 1) * 8 + lr) * QP + (g >> 1) * 8;
    const int boff = ((g >> 1) * 8 + lr) * QP + (g & 1) * 8;

    int buf = 0;
    for (int kt = 0; kt < 16; kt++) {
        cp_wait0();
        __syncthreads();
        if (kt < 15) {
            const size_t base = bh * 2048 + (size_t)(kt + 1) * 128;
            bf16* dh = sK + ((buf ^ 1) * 2 + 0) * 9216;
            bf16* dl = sK + ((buf ^ 1) * 2 + 1) * 9216;
            #pragma unroll
            for (int i = 0; i < 4; i++) {
                int f = i * 256 + t; int row = f >> 3, ck = f & 7;
                cp16(&dh[row * QP + ck * 8], Khi + (base + row) * 64 + ck * 8);
                cp16(&dl[row * QP + ck * 8], Klo + (base + row) * 64 + ck * 8);
            }
            cp_commit();
        }

        float acc[16][4];
        #pragma unroll
        for (int i = 0; i < 16; i++)
            #pragma unroll
            for (int j = 0; j < 4; j++) acc[i][j] = 0.f;

        const unsigned uKh = uK + (unsigned)(((buf * 2 + 0) * 9216) * 2);
        const unsigned uKl = uK + (unsigned)(((buf * 2 + 1) * 9216) * 2);

        #pragma unroll
        for (int ks = 0; ks < 4; ks++) {
            const int kk = ks * 16;
            unsigned ah0, ah1, ah2, ah3, al0, al1, al2, al3;
            ldsm4(ah0, ah1, ah2, ah3, uQh + (unsigned)((aoff + kk) * 2));
            ldsm4(al0, al1, al2, al3, uQl + (unsigned)((aoff + kk) * 2));
            #pragma unroll
            for (int p = 0; p < 8; p++) {
                const unsigned bo = (unsigned)((p * 16 * QP + boff + kk) * 2);
                unsigned bh0, bh1, bh2, bh3, bl0, bl1, bl2, bl3;
                ldsm4(bh0, bh1, bh2, bh3, uKh + bo);
                ldsm4(bl0, bl1, bl2, bl3, uKl + bo);
                mma_bf16(acc[2*p][0], acc[2*p][1], acc[2*p][2], acc[2*p][3],
                         ah0, ah1, ah2, ah3, bh0, bh1);
                mma_bf16(acc[2*p+1][0], acc[2*p+1][1], acc[2*p+1][2], acc[2*p+1][3],
                         ah0, ah1, ah2, ah3, bh2, bh3);
                mma_bf16(acc[2*p][0], acc[2*p][1], acc[2*p][2], acc[2*p][3],
                         al0, al1, al2, al3, bh0, bh1);
                mma_bf16(acc[2*p+1][0], acc[2*p+1][1], acc[2*p+1][2], acc[2*p+1][3],
                         al0, al1, al2, al3, bh2, bh3);
                mma_bf16(acc[2*p][0], acc[2*p][1], acc[2*p][2], acc[2*p][3],
                         ah0, ah1, ah2, ah3, bl0, bl1);
                mma_bf16(acc[2*p+1][0], acc[2*p+1][1], acc[2*p+1][2], acc[2*p+1][3],
                         ah0, ah1, ah2, ah3, bl2, bl3);
            }
        }

        const int kbase = kt * 128;
        float tmA = -INFINITY, tmB = -INFINITY;
        #pragma unroll
        for (int nt = 0; nt < 16; nt++) {
            int kg = kbase + nt * 8 + c0;
            int2 kp = *(const int2*)&kpmb[kg];
            int2 ma = *(const int2*)&maskA[kg];
            int2 mb = *(const int2*)&maskB[kg];
            float v0 = (kp.x && ma.x) ? acc[nt][0] * 0.125f : NEGV;
            float v1 = (kp.y && ma.y) ? acc[nt][1] * 0.125f : NEGV;
            float v2 = (kp.x && mb.x) ? acc[nt][2] * 0.125f : NEGV;
            float v3 = (kp.y && mb.y) ? acc[nt][3] * 0.125f : NEGV;
            acc[nt][0] = v0; acc[nt][1] = v1; acc[nt][2] = v2; acc[nt][3] = v3;
            tmA = fmaxf(tmA, fmaxf(v0, v1));
            tmB = fmaxf(tmB, fmaxf(v2, v3));
        }
        tmA = fmaxf(tmA, __shfl_xor_sync(0xffffffffu, tmA, 1));
        tmA = fmaxf(tmA, __shfl_xor_sync(0xffffffffu, tmA, 2));
        tmB = fmaxf(tmB, __shfl_xor_sync(0xffffffffu, tmB, 1));
        tmB = fmaxf(tmB, __shfl_xor_sync(0xffffffffu, tmB, 2));

        float mnA = fmaxf(mrA, tmA), mnB = fmaxf(mrB, tmB);
        float corA = __expf(mrA - mnA), corB = __expf(mrB - mnB);
        float zlA = 0.f, zlB = 0.f;
        #pragma unroll
        for (int nt = 0; nt < 16; nt++) {
            zlA += __expf(acc[nt][0] - mnA) + __expf(acc[nt][1] - mnA);
            zlB += __expf(acc[nt][2] - mnB) + __expf(acc[nt][3] - mnB);
        }
        zlA += __shfl_xor_sync(0xffffffffu, zlA, 1);
        zlA += __shfl_xor_sync(0xffffffffu, zlA, 2);
        zlB += __shfl_xor_sync(0xffffffffu, zlB, 1);
        zlB += __shfl_xor_sync(0xffffffffu, zlB, 2);
        zrA = zrA * corA + zlA; mrA = mnA;
        zrB = zrB * corB + zlB; mrB = mnB;

        #pragma unroll
        for (int nt = 0; nt < 16; nt++) {
            int kg = kbase + nt * 8 + c0;
            *(float2*)&attnA[kg] = make_float2(acc[nt][0], acc[nt][1]);
            *(float2*)&attnB[kg] = make_float2(acc[nt][2], acc[nt][3]);
        }
        buf ^= 1;
    }

    if ((lane & 3) == 0) {
        stats[bh * S_LEN + qA]     = make_float2(mrA, 1.f / zrA);
        stats[bh * S_LEN + qA + 8] = make_float2(mrB, 1.f / zrB);
    }
}

// ===========================================================================
// attn_av: normalize P in place (required attn output), split P to bf16 hi/lo
// smem, shared-fragment 3-product MMA with VT hi/lo tiles, ctx in (s,b,D).
// ===========================================================================
#define PP 136  // 272B = 17x16B units, odd -> conflict-free ldmatrix
__global__ void __launch_bounds__(256)
attn_av(const bf16* __restrict__ VThi, const bf16* __restrict__ VTlo,
        float* __restrict__ attn, const float2* __restrict__ stats,
        float* __restrict__ ctx)
{
    extern __shared__ __align__(16) bf16 smv[];
    bf16* sPh = smv;
    bf16* sPl = smv + 17408;
    bf16* sVh = smv + 34816;
    bf16* sVl = smv + 43520;
    float2* st = (float2*)(smv + 52224);

    const int t = threadIdx.x;
    const int wid = t >> 5, lane = t & 31;
    const int r0 = lane >> 2, c0 = (lane & 3) * 2;
    const int g  = lane >> 3, lr = lane & 7;
    const int q0 = blockIdx.x * 128, h = blockIdx.y, b = blockIdx.z;
    const size_t bh = (size_t)(b * NHEADS + h);

    if (t < 128) st[t] = stats[bh * S_LEN + q0 + t];

    float* attnp = attn + (bh * S_LEN + q0) * (size_t)S_LEN;
    const bf16* Vh = VThi + bh * (size_t)64 * 2048;
    const bf16* Vl = VTlo + bh * (size_t)64 * 2048;

    const unsigned uPh = smem_u32(sPh), uPl = smem_u32(sPl);
    const unsigned uVh = smem_u32(sVh), uVl = smem_u32(sVl);
    const int aoff = (wid * 16 + (g & 1) * 8 + lr) * PP + (g >> 1) * 8;
    const int boff = ((g >> 1) * 8 + lr) * PP + (g & 1) * 8;

    float acc[8][4];
    #pragma unroll
    for (int i = 0; i < 8; i++)
        #pragma unroll
        for (int j = 0; j < 4; j++) acc[i][j] = 0.f;

    for (int kt = 0; kt < 16; kt++) {
        __syncthreads();

        #pragma unroll
        for (int i = 0; i < 4; i++) {
            int f = i * 256 + t; int row = f >> 4, ck = f & 15;
            cp16(&sVh[row * PP + ck * 8], Vh + (size_t)row * 2048 + kt * 128 + ck * 8);
            cp16(&sVl[row * PP + ck * 8], Vl + (size_t)row * 2048 + kt * 128 + ck * 8);
        }
        cp_commit();

        #pragma unroll
        for (int i = 0; i < 16; i++) {
            int f = i * 256 + t; int row = f >> 5, k4 = (f & 31) * 4;
            float* gp = attnp + (size_t)row * S_LEN + kt * 128 + k4;
            float4 s4 = *(const float4*)gp;
            float2 mz = st[row];
            float4 p4;
            p4.x = __expf(s4.x - mz.x) * mz.y;
            p4.y = __expf(s4.y - mz.x) * mz.y;
            p4.z = __expf(s4.z - mz.x) * mz.y;
            p4.w = __expf(s4.w - mz.x) * mz.y;
            *(float4*)gp = p4;
            bf16 h0 = __float2bfloat16_rn(p4.x), h1 = __float2bfloat16_rn(p4.y);
            bf16 h2 = __float2bfloat16_rn(p4.z), h3 = __float2bfloat16_rn(p4.w);
            bf162 ha; ha.x = h0; ha.y = h1;
            bf162 hb; hb.x = h2; hb.y = h3;
            bf162 la; la.x = __float2bfloat16_rn(p4.x - __bfloat162float(h0));
                      la.y = __float2bfloat16_rn(p4.y - __bfloat162float(h1));
            bf162 lb; lb.x = __float2bfloat16_rn(p4.z - __bfloat162float(h2));
                      lb.y = __float2bfloat16_rn(p4.w - __bfloat162float(h3));
            *(bf162*)&sPh[row * PP + k4]     = ha;
            *(bf162*)&sPh[row * PP + k4 + 2] = hb;
            *(bf162*)&sPl[row * PP + k4]     = la;
            *(bf162*)&sPl[row * PP + k4 + 2] = lb;
        }
        cp_wait0();
        __syncthreads();

        #pragma unroll
        for (int ks = 0; ks < 8; ks++) {
            const int kk = ks * 16;
            unsigned ah0, ah1, ah2, ah3, al0, al1, al2, al3;
            ldsm4(ah0, ah1, ah2, ah3, uPh + (unsigned)((aoff + kk) * 2));
            ldsm4(al0, al1, al2, al3, uPl + (unsigned)((aoff + kk) * 2));
            #pragma unroll
            for (int p = 0; p < 4; p++) {
                const unsigned bo = (unsigned)((p * 16 * PP + boff + kk) * 2);
                unsigned bh0, bh1, bh2, bh3, bl0, bl1, bl2, bl3;
                ldsm4(bh0, bh1, bh2, bh3, uVh + bo);
                ldsm4(bl0, bl1, bl2, bl3, uVl + bo);
                mma_bf16(acc[2*p][0], acc[2*p][1], acc[2*p][2], acc[2*p][3],
                         ah0, ah1, ah2, ah3, bh0, bh1);
                mma_bf16(acc[2*p+1][0], acc[2*p+1][1], acc[2*p+1][2], acc[2*p+1][3],
                         ah0, ah1, ah2, ah3, bh2, bh3);
                mma_bf16(acc[2*p][0], acc[2*p][1], acc[2*p][2], acc[2*p][3],
                         al0, al1, al2, al3, bh0, bh1);
                mma_bf16(acc[2*p+1][0], acc[2*p+1][1], acc[2*p+1][2], acc[2*p+1][3],
                         al0, al1, al2, al3, bh2, bh3);
                mma_bf16(acc[2*p][0], acc[2*p][1], acc[2*p][2], acc[2*p][3],
                         ah0, ah1, ah2, ah3, bl0, bl1);
                mma_bf16(acc[2*p+1][0], acc[2*p+1][1], acc[2*p+1][2], acc[2*p+1][3],
                         ah0, ah1, ah2, ah3, bl2, bl3);
            }
        }
    }

    const int qA = q0 + wid * 16 + r0, qB = qA + 8;
    #pragma unroll
    for (int nt = 0; nt < 8; nt++) {
        int d = h * 64 + nt * 8 + c0;
        *(float2*)&ctx[((size_t)qA * BATCH + b) * DMODEL + d] =
            make_float2(acc[nt][0], acc[nt][1]);
        *(float2*)&ctx[((size_t)qB * BATCH + b) * DMODEL + d] =
            make_float2(acc[nt][2], acc[nt][3]);
    }
}

// ===========================================================================
extern "C" void kernel_launch(void* const* d_in, const int* in_sizes, int n_in,
                              void* d_out, int out_size)
{
    const float* query = (const float*)d_in[0];
    const float* key   = (const float*)d_in[1];
    const float* value = (const float*)d_in[2];
    const int*   mask  = (const int*)  d_in[3];
    const int*   kpm   = (const int*)  d_in[4];
    const float* Wq    = (const float*)d_in[5];
    const float* Wk    = (const float*)d_in[6];
    const float* Wv    = (const float*)d_in[7];
    const float* Wo    = (const float*)d_in[8];
    const float* bo    = (const float*)d_in[9];

    float* out = (float*)d_out;
    const int write_attn = ((size_t)out_size >= OUT_ELEMS + ATTN_ELEMS) ? 1 : 0;

    bf16 *pXh, *pXl, *pWh, *pWl, *pQh, *pQl, *pKh, *pKl, *pVh, *pVl, *pVTh, *pVTl;
    float *pCT, *pAfb;
    float2* pST;
    cudaGetSymbolAddress((void**)&pXh,  g_Xhi);
    cudaGetSymbolAddress((void**)&pXl,  g_Xlo);
    cudaGetSymbolAddress((void**)&pWh,  g_Whi);
    cudaGetSymbolAddress((void**)&pWl,  g_Wlo);
    cudaGetSymbolAddress((void**)&pQh,  g_Qhi);
    cudaGetSymbolAddress((void**)&pQl,  g_Qlo);
    cudaGetSymbolAddress((void**)&pKh,  g_Khi);
    cudaGetSymbolAddress((void**)&pKl,  g_Klo);
    cudaGetSymbolAddress((void**)&pVh,  g_Vhi);
    cudaGetSymbolAddress((void**)&pVl,  g_Vlo);
    cudaGetSymbolAddress((void**)&pVTh, g_VThi);
    cudaGetSymbolAddress((void**)&pVTl, g_VTlo);
    cudaGetSymbolAddress((void**)&pCT,  g_CT);
    cudaGetSymbolAddress((void**)&pST,  g_stats);
    cudaGetSymbolAddress((void**)&pAfb, g_attn_fb);

    float* attn = write_attn ? (out + OUT_ELEMS) : pAfb;

    const int M = S_LEN * BATCH;          // 4096
    dim3 ggrid3(1024 / 128, M / 128, 3);  // batched QKV
    dim3 ggrid1(1024 / 128, M / 128, 1);

    prep_w  <<<dim3(2048, 1, 4), 256>>>(Wq, Wk, Wv, Wo, pWh, pWl);
    prep_qkv<<<dim3(8192, 1, 3), 256>>>(query, key, value, pXh, pXl);

    // Q/K/V projections in ONE launch (dynamic smem)
    cudaFuncSetAttribute(gemm_bf16, cudaFuncAttributeMaxDynamicSharedMemorySize,
                         GEMM_SMEM_BYTES);
    gemm_bf16<<<ggrid3, 256, GEMM_SMEM_BYTES>>>(pXh, pXl, pWh, pWl, 1,
                               nullptr, nullptr, pQh, pQl, pKh, pKl, pVh, pVl);

    // V -> d-major
    dim3 tgrid(2048 / 32, 64 / 32, 32);
    transpose_bf16<<<tgrid, dim3(32, 8)>>>(pVh, pVTh);
    transpose_bf16<<<tgrid, dim3(32, 8)>>>(pVl, pVTl);

    // QK^T + masks + online stats
    const int smq_bytes = 55296 * 2;
    cudaFuncSetAttribute(qk_scores, cudaFuncAttributeMaxDynamicSharedMemorySize, smq_bytes);
    dim3 agrid(S_LEN / 128, NHEADS, BATCH);
    qk_scores<<<agrid, 256, smq_bytes>>>(pQh, pQl, pKh, pKl, mask, kpm, attn, pST);

    // normalize + AV -> ctx
    const int smv_bytes = 52224 * 2 + 128 * 8;
    cudaFuncSetAttribute(attn_av, cudaFuncAttributeMaxDynamicSharedMemorySize, smv_bytes);
    attn_av<<<agrid, 256, smv_bytes>>>(pVTh, pVTl, attn, pST, pCT);

    // output projection (+bias): reuse slab 0 for split ctx
    prep_one<<<8192, 256>>>(pCT, pXh, pXl);
    gemm_bf16<<<ggrid1, 256, GEMM_SMEM_BYTES>>>(pXh, pXl,
                               pWh + 3 * WH_SLAB, pWl + 3 * WH_SLAB,
                               0, out, bo, nullptr, nullptr, nullptr, nullptr,
                               nullptr, nullptr);
}

// round 11
// speedup vs baseline: 1.5529x; 1.0416x over previous
#include <cuda_runtime.h>
#include <cuda_bf16.h>
#include <math.h>

// ---------------- problem constants ----------------
#define S_LEN   2048
#define BATCH   2
#define DMODEL  1024
#define NHEADS  16
#define DK      64
#define NEGV    (-1.0e9f)

#define OUT_ELEMS  ((size_t)S_LEN * BATCH * DMODEL)                 // 4,194,304
#define ATTN_ELEMS ((size_t)BATCH * NHEADS * S_LEN * S_LEN)         // 134,217,728

typedef __nv_bfloat16  bf16;
typedef __nv_bfloat162 bf162;

#define XH_SLAB ((size_t)4096 * 1024)
#define WH_SLAB ((size_t)1024 * 1024)

// ---------------- scratch (static device globals; no runtime alloc) ----------
__device__ bf16  g_Xhi[3 * XH_SLAB];           // activation hi x {q,k,v / ctx}
__device__ bf16  g_Xlo[3 * XH_SLAB];           // activation lo
__device__ bf16  g_Whi[4 * WH_SLAB];           // weight hi x {Wq,Wk,Wv,Wo}
__device__ bf16  g_Wlo[4 * WH_SLAB];           // weight lo
__device__ bf16  g_Qhi[(size_t)32 * 2048 * 64];
__device__ bf16  g_Qlo[(size_t)32 * 2048 * 64];
__device__ bf16  g_Khi[(size_t)32 * 2048 * 64];
__device__ bf16  g_Klo[(size_t)32 * 2048 * 64];
__device__ bf16  g_Vhi[(size_t)32 * 2048 * 64];
__device__ bf16  g_Vlo[(size_t)32 * 2048 * 64];
__device__ bf16  g_VThi[(size_t)32 * 64 * 2048];
__device__ bf16  g_VTlo[(size_t)32 * 64 * 2048];
__device__ float g_CT[(size_t)4096 * 1024];    // context (s,b,D)
__device__ float2 g_stats[32 * 2048];          // per-row {max, 1/Z}
__device__ unsigned g_mbits[2048 * 64];        // mask packed to bits (row q, 64 words)
__device__ unsigned g_kbits[2 * 64];           // key_padding_mask bits per batch
__device__ float g_attn_fb[ATTN_ELEMS];        // fallback if attn not in output

// ---------------- PTX helpers ----------------
__device__ __forceinline__ void cp16(const void* smem_dst, const void* gmem_src) {
    unsigned d = (unsigned)__cvta_generic_to_shared(smem_dst);
    asm volatile("cp.async.cg.shared.global [%0], [%1], 16;" :: "r"(d), "l"(gmem_src));
}
__device__ __forceinline__ void cp_commit() { asm volatile("cp.async.commit_group;"); }
__device__ __forceinline__ void cp_wait0()  { asm volatile("cp.async.wait_group 0;"); }

__device__ __forceinline__ unsigned smem_u32(const void* p) {
    return (unsigned)__cvta_generic_to_shared(p);
}

__device__ __forceinline__ void mma_bf16(float& d0, float& d1, float& d2, float& d3,
                                         unsigned a0, unsigned a1, unsigned a2, unsigned a3,
                                         unsigned b0, unsigned b1)
{
    asm volatile(
        "mma.sync.aligned.m16n8k16.row.col.f32.bf16.bf16.f32 "
        "{%0,%1,%2,%3},{%4,%5,%6,%7},{%8,%9},{%0,%1,%2,%3};\n"
        : "+f"(d0), "+f"(d1), "+f"(d2), "+f"(d3)
        : "r"(a0), "r"(a1), "r"(a2), "r"(a3), "r"(b0), "r"(b1));
}

__device__ __forceinline__ void ldsm4(unsigned& r0, unsigned& r1, unsigned& r2, unsigned& r3,
                                      unsigned addr)
{
    asm volatile("ldmatrix.sync.aligned.m8n8.x4.shared.b16 {%0,%1,%2,%3}, [%4];"
                 : "=r"(r0), "=r"(r1), "=r"(r2), "=r"(r3) : "r"(addr));
}

// ===========================================================================
// prep kernels: fp32 (rows x 1024) -> separate bf16 hi / lo arrays.
// ===========================================================================
__device__ __forceinline__ void split_store2(const float* src, bf16* dh, bf16* dl,
                                             size_t p)
{
    int row = (int)(p >> 9);
    int cp  = (int)(p & 511);
    float2 v = *(const float2*)(src + (size_t)row * 1024 + cp * 2);
    bf16 h0 = __float2bfloat16_rn(v.x);
    bf16 h1 = __float2bfloat16_rn(v.y);
    bf16 l0 = __float2bfloat16_rn(v.x - __bfloat162float(h0));
    bf16 l1 = __float2bfloat16_rn(v.y - __bfloat162float(h1));
    bf162 h2; h2.x = h0; h2.y = h1;
    bf162 l2; l2.x = l0; l2.y = l1;
    *(bf162*)(dh + (size_t)row * 1024 + cp * 2) = h2;
    *(bf162*)(dl + (size_t)row * 1024 + cp * 2) = l2;
}

__global__ void __launch_bounds__(256)
prep_qkv(const float* __restrict__ q, const float* __restrict__ k,
         const float* __restrict__ v, bf16* __restrict__ dh, bf16* __restrict__ dl)
{
    size_t p = (size_t)blockIdx.x * 256 + threadIdx.x;
    if (p >= (size_t)4096 * 512) return;
    const float* src = (blockIdx.z == 0) ? q : (blockIdx.z == 1) ? k : v;
    split_store2(src, dh + blockIdx.z * XH_SLAB, dl + blockIdx.z * XH_SLAB, p);
}

__global__ void __launch_bounds__(256)
prep_w(const float* __restrict__ w0, const float* __restrict__ w1,
       const float* __restrict__ w2, const float* __restrict__ w3,
       bf16* __restrict__ dh, bf16* __restrict__ dl)
{
    size_t p = (size_t)blockIdx.x * 256 + threadIdx.x;
    if (p >= (size_t)1024 * 512) return;
    const float* src = (blockIdx.z == 0) ? w0 : (blockIdx.z == 1) ? w1
                     : (blockIdx.z == 2) ? w2 : w3;
    split_store2(src, dh + blockIdx.z * WH_SLAB, dl + blockIdx.z * WH_SLAB, p);
}

__global__ void __launch_bounds__(256)
prep_one(const float* __restrict__ src, bf16* __restrict__ dh, bf16* __restrict__ dl)
{
    size_t p = (size_t)blockIdx.x * 256 + threadIdx.x;
    if (p >= (size_t)4096 * 512) return;
    split_store2(src, dh, dl, p);
}

// ===========================================================================
// prep_mask: pack int32 masks -> bitmasks. One thread per 32-bit word.
// ===========================================================================
__global__ void __launch_bounds__(256)
prep_mask(const int* __restrict__ mask, const int* __restrict__ kpm,
          unsigned* __restrict__ mb, unsigned* __restrict__ kb)
{
    int id = blockIdx.x * 256 + threadIdx.x;
    if (id < 2048 * 64) {
        const int* src = mask + (size_t)id * 32;
        unsigned w = 0;
        #pragma unroll
        for (int i = 0; i < 32; i += 4) {
            int4 v = *(const int4*)(src + i);
            w |= ((v.x != 0) ? 1u : 0u) << i;
            w |= ((v.y != 0) ? 1u : 0u) << (i + 1);
            w |= ((v.z != 0) ? 1u : 0u) << (i + 2);
            w |= ((v.w != 0) ? 1u : 0u) << (i + 3);
        }
        mb[id] = w;
    }
    if (id < 2 * 64) {
        const int* src = kpm + (size_t)id * 32;
        unsigned w = 0;
        #pragma unroll
        for (int i = 0; i < 32; i += 4) {
            int4 v = *(const int4*)(src + i);
            w |= ((v.x != 0) ? 1u : 0u) << i;
            w |= ((v.y != 0) ? 1u : 0u) << (i + 1);
            w |= ((v.z != 0) ? 1u : 0u) << (i + 2);
            w |= ((v.w != 0) ? 1u : 0u) << (i + 3);
        }
        kb[id] = w;
    }
}

// ===========================================================================
// gemm_bf16: C[m,n] = sum_k (Ah+Al)[m,k]*(Bh+Bl)[n,k] (3 products), K=1024.
// CTA 128x128, BK=32, 8 warps, warp = 16 rows x 128 cols, shared fragments.
// DYNAMIC smem: 2 buffers x 4 tiles (Ah,Al,Bh,Bl) x 128*GP bf16 = 81920 B.
// mode 0: fp32 C (+bias). mode 1: split-bf16 scatter into (b,h,s,d).
// ===========================================================================
#define GP 40   // padded K-stride (80B = 5x16B units, odd -> conflict-free ldmatrix)
#define GTILE (128 * GP)                    // elems per tile
#define GEMM_SMEM_BYTES (2 * 4 * GTILE * 2) // 81920
__global__ void __launch_bounds__(256)
gemm_bf16(const bf16* __restrict__ Xh, const bf16* __restrict__ Xl,
          const bf16* __restrict__ Wh, const bf16* __restrict__ Wl,
          int mode, float* __restrict__ C, const float* __restrict__ bias,
          bf16* __restrict__ Qh, bf16* __restrict__ Ql,
          bf16* __restrict__ Kh, bf16* __restrict__ Kl,
          bf16* __restrict__ Vh, bf16* __restrict__ Vl)
{
    extern __shared__ __align__(16) bf16 smg[];   // [buf][arr][GTILE]

    const int z = blockIdx.z;
    const bf16* Ah = Xh + (size_t)z * XH_SLAB;
    const bf16* Al = Xl + (size_t)z * XH_SLAB;
    const bf16* Bh = Wh + (size_t)z * WH_SLAB;
    const bf16* Bl = Wl + (size_t)z * WH_SLAB;
    bf16* Dhi = (z == 0) ? Qh : (z == 1) ? Kh : Vh;
    bf16* Dlo = (z == 0) ? Ql : (z == 1) ? Kl : Vl;

    const int t = threadIdx.x;
    const int wid = t >> 5, lane = t & 31;
    const int r0 = lane >> 2, c0 = (lane & 3) * 2;
    const int g  = lane >> 3, lr = lane & 7;
    const int bm = blockIdx.y * 128, bn = blockIdx.x * 128;
    const int K = 1024;

    float acc[16][4];
    #pragma unroll
    for (int i = 0; i < 16; i++)
        #pragma unroll
        for (int j = 0; j < 4; j++) acc[i][j] = 0.f;

    auto fill = [&](int buf, int k0) {
        bf16* base = smg + (size_t)buf * 4 * GTILE;
        #pragma unroll
        for (int i = 0; i < 8; i++) {
            int f = i * 256 + t;
            int arr = f >> 9;            // 0=Ah 1=Al 2=Bh 3=Bl
            int idx = f & 511;
            int row = idx >> 2, ck = idx & 3;
            const bf16* gsrc =
                (arr == 0) ? Ah + (size_t)(bm + row) * K + k0 + ck * 8 :
                (arr == 1) ? Al + (size_t)(bm + row) * K + k0 + ck * 8 :
                (arr == 2) ? Bh + (size_t)(bn + row) * K + k0 + ck * 8 :
                             Bl + (size_t)(bn + row) * K + k0 + ck * 8;
            cp16(&base[arr * GTILE + row * GP + ck * 8], gsrc);
        }
        cp_commit();
    };

    fill(0, 0);

    const int aoff = (wid * 16 + (g & 1) * 8 + lr) * GP + (g >> 1) * 8;
    const int boff = ((g >> 1) * 8 + lr) * GP + (g & 1) * 8;

    int buf = 0;
    for (int kt = 0; kt < K / 32; kt++) {
        cp_wait0();
        __syncthreads();
        if (kt + 1 < K / 32) fill(buf ^ 1, (kt + 1) * 32);

        const bf16* sb = smg + (size_t)buf * 4 * GTILE;
        const unsigned uAh = smem_u32(sb + 0 * GTILE);
        const unsigned uAl = smem_u32(sb + 1 * GTILE);
        const unsigned uBh = smem_u32(sb + 2 * GTILE);
        const unsigned uBl = smem_u32(sb + 3 * GTILE);

        #pragma unroll
        for (int ks = 0; ks < 2; ks++) {
            const int kk = ks * 16;
            unsigned ah0, ah1, ah2, ah3, al0, al1, al2, al3;
            ldsm4(ah0, ah1, ah2, ah3, uAh + (unsigned)((aoff + kk) * 2));
            ldsm4(al0, al1, al2, al3, uAl + (unsigned)((aoff + kk) * 2));
            #pragma unroll
            for (int p = 0; p < 8; p++) {
                const unsigned bo = (unsigned)((p * 16 * GP + boff + kk) * 2);
                unsigned bh0, bh1, bh2, bh3, bl0, bl1, bl2, bl3;
                ldsm4(bh0, bh1, bh2, bh3, uBh + bo);
                ldsm4(bl0, bl1, bl2, bl3, uBl + bo);
                mma_bf16(acc[2*p][0], acc[2*p][1], acc[2*p][2], acc[2*p][3],
                         ah0, ah1, ah2, ah3, bh0, bh1);
                mma_bf16(acc[2*p+1][0], acc[2*p+1][1], acc[2*p+1][2], acc[2*p+1][3],
                         ah0, ah1, ah2, ah3, bh2, bh3);
                mma_bf16(acc[2*p][0], acc[2*p][1], acc[2*p][2], acc[2*p][3],
                         al0, al1, al2, al3, bh0, bh1);
                mma_bf16(acc[2*p+1][0], acc[2*p+1][1], acc[2*p+1][2], acc[2*p+1][3],
                         al0, al1, al2, al3, bh2, bh3);
                mma_bf16(acc[2*p][0], acc[2*p][1], acc[2*p][2], acc[2*p][3],
                         ah0, ah1, ah2, ah3, bl0, bl1);
                mma_bf16(acc[2*p+1][0], acc[2*p+1][1], acc[2*p+1][2], acc[2*p+1][3],
                         ah0, ah1, ah2, ah3, bl2, bl3);
            }
        }
        __syncthreads();
        buf ^= 1;
    }

    const int mA = bm + wid * 16 + r0, mB = mA + 8;
    #pragma unroll
    for (int nt = 0; nt < 16; nt++) {
        int n = bn + nt * 8 + c0;
        if (mode == 0) {
            float bx = bias[n], by = bias[n + 1];
            *(float2*)(C + (size_t)mA * 1024 + n) = make_float2(acc[nt][0] + bx, acc[nt][1] + by);
            *(float2*)(C + (size_t)mB * 1024 + n) = make_float2(acc[nt][2] + bx, acc[nt][3] + by);
        } else {
            int h = n >> 6, d = n & 63;
            #pragma unroll
            for (int rr = 0; rr < 2; rr++) {
                int m = rr ? mB : mA;
                float v0 = acc[nt][rr * 2], v1 = acc[nt][rr * 2 + 1];
                int s = m >> 1, b = m & 1;
                size_t off = (((size_t)(b * NHEADS + h) * S_LEN) + s) * 64 + d;
                bf16 h0 = __float2bfloat16_rn(v0);
                bf16 h1 = __float2bfloat16_rn(v1);
                bf16 l0 = __float2bfloat16_rn(v0 - __bfloat162float(h0));
                bf16 l1 = __float2bfloat16_rn(v1 - __bfloat162float(h1));
                bf162 hh; hh.x = h0; hh.y = h1;
                bf162 ll; ll.x = l0; ll.y = l1;
                *(bf162*)(Dhi + off) = hh;
                *(bf162*)(Dlo + off) = ll;
            }
        }
    }
}

// ===========================================================================
// transpose_bf16: (b,h,s,64) -> (b,h,64,2048)
// ===========================================================================
__global__ void __launch_bounds__(256)
transpose_bf16(const bf16* __restrict__ src, bf16* __restrict__ dst)
{
    __shared__ bf16 tl[32][34];
    const int bh = blockIdx.z;
    const bf16* s = src + (size_t)bh * 2048 * 64;
    bf16*       d = dst + (size_t)bh * 64 * 2048;
    const int s0 = blockIdx.x * 32, d0 = blockIdx.y * 32;
    const int x = threadIdx.x, y = threadIdx.y;
    #pragma unroll
    for (int i = 0; i < 32; i += 8)
        tl[y + i][x] = s[(size_t)(s0 + y + i) * 64 + d0 + x];
    __syncthreads();
    #pragma unroll
    for (int i = 0; i < 32; i += 8)
        d[(size_t)(d0 + y + i) * 2048 + s0 + x] = tl[x][y + i];
}

// ===========================================================================
// qk_scores: per CTA (128 q rows, h, b): shared-fragment 3-product MMA,
// bitmask + scale + online softmax stats, raw masked scores -> attn buffer.
// __launch_bounds__(256,2): 2 CTAs/SM (smem 110592 x2 fits 228KB).
// ===========================================================================
#define QP 72   // 144B = 9x16B units, odd -> conflict-free ldmatrix
__global__ void __launch_bounds__(256, 2)
qk_scores(const bf16* __restrict__ Qhi, const bf16* __restrict__ Qlo,
          const bf16* __restrict__ Khi, const bf16* __restrict__ Klo,
          const unsigned* __restrict__ mbits, const unsigned* __restrict__ kbits,
          float* __restrict__ attn, float2* __restrict__ stats)
{
    extern __shared__ __align__(16) bf16 smq[];
    bf16* sQh = smq;
    bf16* sQl = smq + 9216;
    bf16* sK  = smq + 18432;    // [buf][hi/lo] x 9216

    const int t = threadIdx.x;
    const int wid = t >> 5, lane = t & 31;
    const int r0 = lane >> 2, c0 = (lane & 3) * 2;
    const int g  = lane >> 3, lr = lane & 7;
    const int q0 = blockIdx.x * 128, h = blockIdx.y, b = blockIdx.z;
    const size_t bh = (size_t)(b * NHEADS + h);

    {
        const size_t base = bh * 2048 + q0;
        #pragma unroll
        for (int i = 0; i < 4; i++) {
            int f = i * 256 + t; int row = f >> 3, ck = f & 7;
            cp16(&sQh[row * QP + ck * 8], Qhi + (base + row) * 64 + ck * 8);
            cp16(&sQl[row * QP + ck * 8], Qlo + (base + row) * 64 + ck * 8);
        }
    }
    {
        const size_t base = bh * 2048;
        #pragma unroll
        for (int i = 0; i < 4; i++) {
            int f = i * 256 + t; int row = f >> 3, ck = f & 7;
            cp16(&sK[0 * 9216 + row * QP + ck * 8], Khi + (base + row) * 64 + ck * 8);
            cp16(&sK[1 * 9216 + row * QP + ck * 8], Klo + (base + row) * 64 + ck * 8);
        }
    }
    cp_commit();

    const unsigned uQh = smem_u32(sQh), uQl = smem_u32(sQl), uK = smem_u32(sK);

    float mrA = -INFINITY, zrA = 0.f, mrB = -INFINITY, zrB = 0.f;
    const int qA = q0 + wid * 16 + r0;
    const unsigned* mbA = mbits + (size_t)qA * 64;
    const unsigned* mbB = mbits + (size_t)(qA + 8) * 64;
    const unsigned* kb  = kbits + b * 64;
    float* attnA = attn + (bh * S_LEN + qA) * (size_t)S_LEN;
    float* attnB = attnA + (size_t)8 * S_LEN;

    const int aoff = (wid * 16 + (g & 1) * 8 + lr) * QP + (g >> 1) * 8;
    const int boff = ((g >> 1) * 8 + lr) * QP + (g & 1) * 8;

    int buf = 0;
    for (int kt = 0; kt < 16; kt++) {
        cp_wait0();
        __syncthreads();
        if (kt < 15) {
            const size_t base = bh * 2048 + (size_t)(kt + 1) * 128;
            bf16* dh = sK + ((buf ^ 1) * 2 + 0) * 9216;
            bf16* dl = sK + ((buf ^ 1) * 2 + 1) * 9216;
            #pragma unroll
            for (int i = 0; i < 4; i++) {
                int f = i * 256 + t; int row = f >> 3, ck = f & 7;
                cp16(&dh[row * QP + ck * 8], Khi + (base + row) * 64 + ck * 8);
                cp16(&dl[row * QP + ck * 8], Klo + (base + row) * 64 + ck * 8);
            }
            cp_commit();
        }

        float acc[16][4];
        #pragma unroll
        for (int i = 0; i < 16; i++)
            #pragma unroll
            for (int j = 0; j < 4; j++) acc[i][j] = 0.f;

        const unsigned uKh = uK + (unsigned)(((buf * 2 + 0) * 9216) * 2);
        const unsigned uKl = uK + (unsigned)(((buf * 2 + 1) * 9216) * 2);

        #pragma unroll
        for (int ks = 0; ks < 4; ks++) {
            const int kk = ks * 16;
            unsigned ah0, ah1, ah2, ah3, al0, al1, al2, al3;
            ldsm4(ah0, ah1, ah2, ah3, uQh + (unsigned)((aoff + kk) * 2));
            ldsm4(al0, al1, al2, al3, uQl + (unsigned)((aoff + kk) * 2));
            #pragma unroll
            for (int p = 0; p < 8; p++) {
                const unsigned bo = (unsigned)((p * 16 * QP + boff + kk) * 2);
                unsigned bh0, bh1, bh2, bh3, bl0, bl1, bl2, bl3;
                ldsm4(bh0, bh1, bh2, bh3, uKh + bo);
                ldsm4(bl0, bl1, bl2, bl3, uKl + bo);
                mma_bf16(acc[2*p][0], acc[2*p][1], acc[2*p][2], acc[2*p][3],
                         ah0, ah1, ah2, ah3, bh0, bh1);
                mma_bf16(acc[2*p+1][0], acc[2*p+1][1], acc[2*p+1][2], acc[2*p+1][3],
                         ah0, ah1, ah2, ah3, bh2, bh3);
                mma_bf16(acc[2*p][0], acc[2*p][1], acc[2*p][2], acc[2*p][3],
                         al0, al1, al2, al3, bh0, bh1);
                mma_bf16(acc[2*p+1][0], acc[2*p+1][1], acc[2*p+1][2], acc[2*p+1][3],
                         al0, al1, al2, al3, bh2, bh3);
                mma_bf16(acc[2*p][0], acc[2*p][1], acc[2*p][2], acc[2*p][3],
                         ah0, ah1, ah2, ah3, bl0, bl1);
                mma_bf16(acc[2*p+1][0], acc[2*p+1][1], acc[2*p+1][2], acc[2*p+1][3],
                         ah0, ah1, ah2, ah3, bl2, bl3);
            }
        }

        // ---- epilogue: bitmask, scale, online stats, raw score store ----
        const int kbase = kt * 128;
        unsigned wA[4], wB[4], wK2[4];
        #pragma unroll
        for (int j = 0; j < 4; j++) {
            wA[j]  = mbA[kt * 4 + j];
            wB[j]  = mbB[kt * 4 + j];
            wK2[j] = kb [kt * 4 + j];
        }

        float tmA = -INFINITY, tmB = -INFINITY;
        #pragma unroll
        for (int nt = 0; nt < 16; nt++) {
            int cc = nt * 8 + c0;
            int wi = cc >> 5, sh = cc & 31;
            unsigned okA = (wA[wi] >> sh) & (wK2[wi] >> sh);
            unsigned okB = (wB[wi] >> sh) & (wK2[wi] >> sh);
            float v0 = (okA & 1) ? acc[nt][0] * 0.125f : NEGV;
            float v1 = (okA & 2) ? acc[nt][1] * 0.125f : NEGV;
            float v2 = (okB & 1) ? acc[nt][2] * 0.125f : NEGV;
            float v3 = (okB & 2) ? acc[nt][3] * 0.125f : NEGV;
            acc[nt][0] = v0; acc[nt][1] = v1; acc[nt][2] = v2; acc[nt][3] = v3;
            tmA = fmaxf(tmA, fmaxf(v0, v1));
            tmB = fmaxf(tmB, fmaxf(v2, v3));
        }
        tmA = fmaxf(tmA, __shfl_xor_sync(0xffffffffu, tmA, 1));
        tmA = fmaxf(tmA, __shfl_xor_sync(0xffffffffu, tmA, 2));
        tmB = fmaxf(tmB, __shfl_xor_sync(0xffffffffu, tmB, 1));
        tmB = fmaxf(tmB, __shfl_xor_sync(0xffffffffu, tmB, 2));

        float mnA = fmaxf(mrA, tmA), mnB = fmaxf(mrB, tmB);
        float corA = __expf(mrA - mnA), corB = __expf(mrB - mnB);
        float zlA = 0.f, zlB = 0.f;
        #pragma unroll
        for (int nt = 0; nt < 16; nt++) {
            zlA += __expf(acc[nt][0] - mnA) + __expf(acc[nt][1] - mnA);
            zlB += __expf(acc[nt][2] - mnB) + __expf(acc[nt][3] - mnB);
        }
        zlA += __shfl_xor_sync(0xffffffffu, zlA, 1);
        zlA += __shfl_xor_sync(0xffffffffu, zlA, 2);
        zlB += __shfl_xor_sync(0xffffffffu, zlB, 1);
        zlB += __shfl_xor_sync(0xffffffffu, zlB, 2);
        zrA = zrA * corA + zlA; mrA = mnA;
        zrB = zrB * corB + zlB; mrB = mnB;

        #pragma unroll
        for (int nt = 0; nt < 16; nt++) {
            int kg = kbase + nt * 8 + c0;
            *(float2*)&attnA[kg] = make_float2(acc[nt][0], acc[nt][1]);
            *(float2*)&attnB[kg] = make_float2(acc[nt][2], acc[nt][3]);
        }
        buf ^= 1;
    }

    if ((lane & 3) == 0) {
        stats[bh * S_LEN + qA]     = make_float2(mrA, 1.f / zrA);
        stats[bh * S_LEN + qA + 8] = make_float2(mrB, 1.f / zrB);
    }
}

// ===========================================================================
// attn_av: normalize P in place (required attn output), split P to bf16 hi/lo
// smem, shared-fragment 3-product MMA with VT hi/lo tiles, ctx in (s,b,D).
// __launch_bounds__(256,2): 2 CTAs/SM.
// ===========================================================================
#define PP 136  // 272B = 17x16B units, odd -> conflict-free ldmatrix
__global__ void __launch_bounds__(256, 2)
attn_av(const bf16* __restrict__ VThi, const bf16* __restrict__ VTlo,
        float* __restrict__ attn, const float2* __restrict__ stats,
        float* __restrict__ ctx)
{
    extern __shared__ __align__(16) bf16 smv[];
    bf16* sPh = smv;
    bf16* sPl = smv + 17408;
    bf16* sVh = smv + 34816;
    bf16* sVl = smv + 43520;
    float2* st = (float2*)(smv + 52224);

    const int t = threadIdx.x;
    const int wid = t >> 5, lane = t & 31;
    const int r0 = lane >> 2, c0 = (lane & 3) * 2;
    const int g  = lane >> 3, lr = lane & 7;
    const int q0 = blockIdx.x * 128, h = blockIdx.y, b = blockIdx.z;
    const size_t bh = (size_t)(b * NHEADS + h);

    if (t < 128) st[t] = stats[bh * S_LEN + q0 + t];

    float* attnp = attn + (bh * S_LEN + q0) * (size_t)S_LEN;
    const bf16* Vh = VThi + bh * (size_t)64 * 2048;
    const bf16* Vl = VTlo + bh * (size_t)64 * 2048;

    const unsigned uPh = smem_u32(sPh), uPl = smem_u32(sPl);
    const unsigned uVh = smem_u32(sVh), uVl = smem_u32(sVl);
    const int aoff = (wid * 16 + (g & 1) * 8 + lr) * PP + (g >> 1) * 8;
    const int boff = ((g >> 1) * 8 + lr) * PP + (g & 1) * 8;

    float acc[8][4];
    #pragma unroll
    for (int i = 0; i < 8; i++)
        #pragma unroll
        for (int j = 0; j < 4; j++) acc[i][j] = 0.f;

    for (int kt = 0; kt < 16; kt++) {
        __syncthreads();

        #pragma unroll
        for (int i = 0; i < 4; i++) {
            int f = i * 256 + t; int row = f >> 4, ck = f & 15;
            cp16(&sVh[row * PP + ck * 8], Vh + (size_t)row * 2048 + kt * 128 + ck * 8);
            cp16(&sVl[row * PP + ck * 8], Vl + (size_t)row * 2048 + kt * 128 + ck * 8);
        }
        cp_commit();

        #pragma unroll
        for (int i = 0; i < 16; i++) {
            int f = i * 256 + t; int row = f >> 5, k4 = (f & 31) * 4;
            float* gp = attnp + (size_t)row * S_LEN + kt * 128 + k4;
            float4 s4 = *(const float4*)gp;
            float2 mz = st[row];
            float4 p4;
            p4.x = __expf(s4.x - mz.x) * mz.y;
            p4.y = __expf(s4.y - mz.x) * mz.y;
            p4.z = __expf(s4.z - mz.x) * mz.y;
            p4.w = __expf(s4.w - mz.x) * mz.y;
            *(float4*)gp = p4;
            bf16 h0 = __float2bfloat16_rn(p4.x), h1 = __float2bfloat16_rn(p4.y);
            bf16 h2 = __float2bfloat16_rn(p4.z), h3 = __float2bfloat16_rn(p4.w);
            bf162 ha; ha.x = h0; ha.y = h1;
            bf162 hb; hb.x = h2; hb.y = h3;
            bf162 la; la.x = __float2bfloat16_rn(p4.x - __bfloat162float(h0));
                      la.y = __float2bfloat16_rn(p4.y - __bfloat162float(h1));
            bf162 lb; lb.x = __float2bfloat16_rn(p4.z - __bfloat162float(h2));
                      lb.y = __float2bfloat16_rn(p4.w - __bfloat162float(h3));
            *(bf162*)&sPh[row * PP + k4]     = ha;
            *(bf162*)&sPh[row * PP + k4 + 2] = hb;
            *(bf162*)&sPl[row * PP + k4]     = la;
            *(bf162*)&sPl[row * PP + k4 + 2] = lb;
        }
        cp_wait0();
        __syncthreads();

        #pragma unroll
        for (int ks = 0; ks < 8; ks++) {
            const int kk = ks * 16;
            unsigned ah0, ah1, ah2, ah3, al0, al1, al2, al3;
            ldsm4(ah0, ah1, ah2, ah3, uPh + (unsigned)((aoff + kk) * 2));
            ldsm4(al0, al1, al2, al3, uPl + (unsigned)((aoff + kk) * 2));
            #pragma unroll
            for (int p = 0; p < 4; p++) {
                const unsigned bo = (unsigned)((p * 16 * PP + boff + kk) * 2);
                unsigned bh0, bh1, bh2, bh3, bl0, bl1, bl2, bl3;
                ldsm4(bh0, bh1, bh2, bh3, uVh + bo);
                ldsm4(bl0, bl1, bl2, bl3, uVl + bo);
                mma_bf16(acc[2*p][0], acc[2*p][1], acc[2*p][2], acc[2*p][3],
                         ah0, ah1, ah2, ah3, bh0, bh1);
                mma_bf16(acc[2*p+1][0], acc[2*p+1][1], acc[2*p+1][2], acc[2*p+1][3],
                         ah0, ah1, ah2, ah3, bh2, bh3);
                mma_bf16(acc[2*p][0], acc[2*p][1], acc[2*p][2], acc[2*p][3],
                         al0, al1, al2, al3, bh0, bh1);
                mma_bf16(acc[2*p+1][0], acc[2*p+1][1], acc[2*p+1][2], acc[2*p+1][3],
                         al0, al1, al2, al3, bh2, bh3);
                mma_bf16(acc[2*p][0], acc[2*p][1], acc[2*p][2], acc[2*p][3],
                         ah0, ah1, ah2, ah3, bl0, bl1);
                mma_bf16(acc[2*p+1][0], acc[2*p+1][1], acc[2*p+1][2], acc[2*p+1][3],
                         ah0, ah1, ah2, ah3, bl2, bl3);
            }
        }
    }

    const int qA = q0 + wid * 16 + r0, qB = qA + 8;
    #pragma unroll
    for (int nt = 0; nt < 8; nt++) {
        int d = h * 64 + nt * 8 + c0;
        *(float2*)&ctx[((size_t)qA * BATCH + b) * DMODEL + d] =
            make_float2(acc[nt][0], acc[nt][1]);
        *(float2*)&ctx[((size_t)qB * BATCH + b) * DMODEL + d] =
            make_float2(acc[nt][2], acc[nt][3]);
    }
}

// ===========================================================================
extern "C" void kernel_launch(void* const* d_in, const int* in_sizes, int n_in,
                              void* d_out, int out_size)
{
    const float* query = (const float*)d_in[0];
    const float* key   = (const float*)d_in[1];
    const float* value = (const float*)d_in[2];
    const int*   mask  = (const int*)  d_in[3];
    const int*   kpm   = (const int*)  d_in[4];
    const float* Wq    = (const float*)d_in[5];
    const float* Wk    = (const float*)d_in[6];
    const float* Wv    = (const float*)d_in[7];
    const float* Wo    = (const float*)d_in[8];
    const float* bo    = (const float*)d_in[9];

    float* out = (float*)d_out;
    const int write_attn = ((size_t)out_size >= OUT_ELEMS + ATTN_ELEMS) ? 1 : 0;

    bf16 *pXh, *pXl, *pWh, *pWl, *pQh, *pQl, *pKh, *pKl, *pVh, *pVl, *pVTh, *pVTl;
    float *pCT, *pAfb;
    float2* pST;
    unsigned *pMB, *pKB;
    cudaGetSymbolAddress((void**)&pXh,  g_Xhi);
    cudaGetSymbolAddress((void**)&pXl,  g_Xlo);
    cudaGetSymbolAddress((void**)&pWh,  g_Whi);
    cudaGetSymbolAddress((void**)&pWl,  g_Wlo);
    cudaGetSymbolAddress((void**)&pQh,  g_Qhi);
    cudaGetSymbolAddress((void**)&pQl,  g_Qlo);
    cudaGetSymbolAddress((void**)&pKh,  g_Khi);
    cudaGetSymbolAddress((void**)&pKl,  g_Klo);
    cudaGetSymbolAddress((void**)&pVh,  g_Vhi);
    cudaGetSymbolAddress((void**)&pVl,  g_Vlo);
    cudaGetSymbolAddress((void**)&pVTh, g_VThi);
    cudaGetSymbolAddress((void**)&pVTl, g_VTlo);
    cudaGetSymbolAddress((void**)&pCT,  g_CT);
    cudaGetSymbolAddress((void**)&pST,  g_stats);
    cudaGetSymbolAddress((void**)&pMB,  g_mbits);
    cudaGetSymbolAddress((void**)&pKB,  g_kbits);
    cudaGetSymbolAddress((void**)&pAfb, g_attn_fb);

    float* attn = write_attn ? (out + OUT_ELEMS) : pAfb;

    const int M = S_LEN * BATCH;          // 4096
    dim3 ggrid3(1024 / 128, M / 128, 3);  // batched QKV
    dim3 ggrid1(1024 / 128, M / 128, 1);

    prep_w   <<<dim3(2048, 1, 4), 256>>>(Wq, Wk, Wv, Wo, pWh, pWl);
    prep_qkv <<<dim3(8192, 1, 3), 256>>>(query, key, value, pXh, pXl);
    prep_mask<<<512, 256>>>(mask, kpm, pMB, pKB);

    // Q/K/V projections in ONE launch (dynamic smem)
    cudaFuncSetAttribute(gemm_bf16, cudaFuncAttributeMaxDynamicSharedMemorySize,
                         GEMM_SMEM_BYTES);
    gemm_bf16<<<ggrid3, 256, GEMM_SMEM_BYTES>>>(pXh, pXl, pWh, pWl, 1,
                               nullptr, nullptr, pQh, pQl, pKh, pKl, pVh, pVl);

    // V -> d-major
    dim3 tgrid(2048 / 32, 64 / 32, 32);
    transpose_bf16<<<tgrid, dim3(32, 8)>>>(pVh, pVTh);
    transpose_bf16<<<tgrid, dim3(32, 8)>>>(pVl, pVTl);

    // QK^T + bitmasks + online stats
    const int smq_bytes = 55296 * 2;
    cudaFuncSetAttribute(qk_scores, cudaFuncAttributeMaxDynamicSharedMemorySize, smq_bytes);
    dim3 agrid(S_LEN / 128, NHEADS, BATCH);
    qk_scores<<<agrid, 256, smq_bytes>>>(pQh, pQl, pKh, pKl, pMB, pKB, attn, pST);

    // normalize + AV -> ctx
    const int smv_bytes = 52224 * 2 + 128 * 8;
    cudaFuncSetAttribute(attn_av, cudaFuncAttributeMaxDynamicSharedMemorySize, smv_bytes);
    attn_av<<<agrid, 256, smv_bytes>>>(pVTh, pVTl, attn, pST, pCT);

    // output projection (+bias): reuse slab 0 for split ctx
    prep_one<<<8192, 256>>>(pCT, pXh, pXl);
    gemm_bf16<<<ggrid1, 256, GEMM_SMEM_BYTES>>>(pXh, pXl,
                               pWh + 3 * WH_SLAB, pWl + 3 * WH_SLAB,
                               0, out, bo, nullptr, nullptr, nullptr, nullptr,
                               nullptr, nullptr);
}